// round 4
// baseline (speedup 1.0000x reference)
#include <cuda_runtime.h>
#include <cstdint>

#define N_NODES 40000
#define N_EDGES 640000
#define NUM_GRAPHS 64
#define NE_TOT (N_EDGES + N_NODES)

// ---------------- device scratch (referenced directly by symbol) ----------------
__device__ float g_bufA[N_NODES * 128];     // GEMM output h
__device__ float g_bufB[N_NODES * 128];     // aggregation output / next input
__device__ float g_als[N_NODES * 4];
__device__ float g_ald[N_NODES * 4];
__device__ int   g_deg[N_NODES];            // degree, then reused as cursor
__device__ int   g_rs[N_NODES + 1];         // CSR row starts (by dst)
__device__ int   g_srcs[NE_TOT];            // CSR src list (incl. self loops)
__device__ float g_g[NUM_GRAPHS * 32];      // pooled graph features
__device__ int   g_is64;                    // 1 if edge_index/batch are int64

// ---------------- index helpers ----------------
__device__ __forceinline__ int load_idx(const void* p, int i, bool is64) {
    return is64 ? (int)((const long long*)p)[i] : ((const int*)p)[i];
}

// ---------------- dtype detection + zero ----------------
// Reads the first 2E int32 words of edge_index. If dtype is int64 (values <
// 2^31), every odd word (high half) is 0. If int32, odd words are node ids.
__global__ void k_detect(const void* __restrict__ ei) {
    int i = blockIdx.x * blockDim.x + threadIdx.x;
    if (i == 0) { /* g_is64 preset by k_zero */ }
    int idx = 2 * i + 1;
    if (idx < 2 * N_EDGES) {
        if (((const int*)ei)[idx] != 0) g_is64 = 0;   // racing stores of 0: fine
    }
}

__global__ void k_zero_deg(int preset64) {
    int i = blockIdx.x * blockDim.x + threadIdx.x;
    if (i < N_NODES) g_deg[i] = 0;
    if (i == 0 && preset64) g_is64 = 1;
}

// ---------------- CSR build ----------------
__global__ void k_hist(const void* __restrict__ ei) {
    int i = blockIdx.x * blockDim.x + threadIdx.x;
    if (i >= NE_TOT) return;
    const bool is64 = (g_is64 != 0);
    int d = (i < N_EDGES) ? load_idx(ei, N_EDGES + i, is64) : (i - N_EDGES);
    if ((unsigned)d < (unsigned)N_NODES) atomicAdd(&g_deg[d], 1);
}

__global__ void k_scan() {
    __shared__ int part[1024];
    const int t = threadIdx.x;
    const int per = (N_NODES + 1023) / 1024;
    const int base = t * per;
    int s = 0;
    for (int i = 0; i < per; i++) {
        int idx = base + i;
        if (idx < N_NODES) s += g_deg[idx];
    }
    part[t] = s;
    __syncthreads();
    for (int o = 1; o < 1024; o <<= 1) {
        int v = (t >= o) ? part[t - o] : 0;
        __syncthreads();
        part[t] += v;
        __syncthreads();
    }
    int prefix = (t == 0) ? 0 : part[t - 1];
    for (int i = 0; i < per; i++) {
        int idx = base + i;
        if (idx < N_NODES) { g_rs[idx] = prefix; prefix += g_deg[idx]; }
    }
    if (t == 1023) g_rs[N_NODES] = part[1023];
}

__global__ void k_scatter(const void* __restrict__ ei) {
    int i = blockIdx.x * blockDim.x + threadIdx.x;
    if (i >= NE_TOT) return;
    const bool is64 = (g_is64 != 0);
    int s, d;
    if (i < N_EDGES) {
        s = load_idx(ei, i, is64);
        d = load_idx(ei, N_EDGES + i, is64);
    } else {
        s = d = i - N_EDGES;
    }
    if ((unsigned)d >= (unsigned)N_NODES || (unsigned)s >= (unsigned)N_NODES) return;
    int pos = g_rs[d] + atomicAdd(&g_deg[d], 1);
    g_srcs[pos] = s;
}

// ---------------- GEMM (+ fused input ELU+bias, fused als/ald) ----------------
// SRC: 0 = external x, 1 = g_bufB. Output always g_bufA + g_als/g_ald.
template <int M, bool ACT, int SRC>
__global__ __launch_bounds__(128) void k_gemm(
    const float* __restrict__ xin, const float* __restrict__ W,
    const float* __restrict__ bprev,
    const float* __restrict__ a_src, const float* __restrict__ a_dst) {
    constexpr int G = 128 / M;
    constexpr int RPP = 8 * G;
    constexpr int H = M / 32;
    const int t = threadIdx.x;
    const int col = t % M;
    const int grp = t / M;
    const int head = col >> 5;
    const int c = col & 31;
    __shared__ float xs[RPP][128];
    const float asv = a_src[head * 32 + c];
    const float adv = a_dst[head * 32 + c];
    const int rowblock = blockIdx.x * (4 * RPP);
    const float* __restrict__ in = (SRC == 0) ? xin : g_bufB;

    for (int pass = 0; pass < 4; ++pass) {
        const int rbase = rowblock + pass * RPP;
        __syncthreads();
        for (int j = t; j < RPP * 128; j += 128) {
            int r = rbase + (j >> 7);
            float v = (r < N_NODES) ? in[(size_t)r * 128 + (j & 127)] : 0.f;
            if (ACT) {
                v += bprev[j & 127];
                v = v > 0.f ? v : expm1f(v);
            }
            xs[j >> 7][j & 127] = v;
        }
        __syncthreads();
        float acc[8] = {0, 0, 0, 0, 0, 0, 0, 0};
        const int r0 = grp * 8;
#pragma unroll 4
        for (int k = 0; k < 128; ++k) {
            float w = W[k * M + col];
#pragma unroll
            for (int r = 0; r < 8; ++r) acc[r] += xs[r0 + r][k] * w;
        }
#pragma unroll
        for (int r = 0; r < 8; ++r) {
            int row = rbase + r0 + r;   // warp-uniform
            if (row < N_NODES) {
                g_bufA[(size_t)row * M + col] = acc[r];
                float s1 = acc[r] * asv, s2 = acc[r] * adv;
#pragma unroll
                for (int o = 16; o; o >>= 1) {
                    s1 += __shfl_xor_sync(0xffffffffu, s1, o);
                    s2 += __shfl_xor_sync(0xffffffffu, s2, o);
                }
                if (c == 0) {
                    g_als[row * H + head] = s1;
                    g_ald[row * H + head] = s2;
                }
            }
        }
    }
}

// ---------------- GAT aggregation: one warp per destination node ----------------
template <int H>
__global__ __launch_bounds__(256) void k_agg() {
    int d = (blockIdx.x * blockDim.x + threadIdx.x) >> 5;
    if (d >= N_NODES) return;
    const int lane = threadIdx.x & 31;
    const int beg = g_rs[d], end = g_rs[d + 1];
    constexpr int CT = H * 32;
    constexpr int FPL = CT / 32;
    const int head = (lane * FPL) >> 5;

    float aldd[H], mx[H];
#pragma unroll
    for (int h = 0; h < H; h++) { aldd[h] = g_ald[d * H + h]; mx[h] = -1e30f; }

    // phase A: per-head max (lane-strided over in-edges)
    for (int j = beg + lane; j < end; j += 32) {
        int s = g_srcs[j];
#pragma unroll
        for (int h = 0; h < H; h++) {
            float e = g_als[s * H + h] + aldd[h];
            e = e > 0.f ? e : 0.2f * e;
            mx[h] = fmaxf(mx[h], e);
        }
    }
#pragma unroll
    for (int h = 0; h < H; h++)
#pragma unroll
        for (int o = 16; o; o >>= 1)
            mx[h] = fmaxf(mx[h], __shfl_xor_sync(0xffffffffu, mx[h], o));

    // phase B: p = exp(e - m); den += p; acc += p * h[src]
    const float m = mx[head];
    const float aldh = aldd[head];
    float den = 0.f;
    float acc[FPL];
#pragma unroll
    for (int f = 0; f < FPL; f++) acc[f] = 0.f;

    for (int j = beg; j < end; ++j) {
        int s = g_srcs[j];
        float e = g_als[s * H + head] + aldh;
        e = e > 0.f ? e : 0.2f * e;
        float p = __expf(e - m);
        den += p;
        const float* hr = g_bufA + (size_t)s * CT + lane * FPL;
        if (FPL == 4) {
            float4 v = *reinterpret_cast<const float4*>(hr);
            acc[0] += p * v.x; acc[1] += p * v.y;
            acc[2] += p * v.z; acc[3] += p * v.w;
        } else {
            acc[0] += p * hr[0];
        }
    }
    float inv = 1.f / fmaxf(den, 1e-16f);
    float* orow = g_bufB + (size_t)d * CT + lane * FPL;
#pragma unroll
    for (int f = 0; f < FPL; f++) orow[f] = acc[f] * inv;
}

// ---------------- global mean pool (batch sorted, fused ELU+bias) ----------------
__global__ __launch_bounds__(256) void k_pool(
    const void* __restrict__ batch, const float* __restrict__ b2) {
    const bool is64 = (g_is64 != 0);
    const int gi = blockIdx.x;
    int lo = 0, hi = N_NODES;
    while (lo < hi) { int mid = (lo + hi) >> 1;
        if (load_idx(batch, mid, is64) < gi) lo = mid + 1; else hi = mid; }
    const int start = lo;
    lo = start; hi = N_NODES;
    while (lo < hi) { int mid = (lo + hi) >> 1;
        if (load_idx(batch, mid, is64) < gi + 1) lo = mid + 1; else hi = mid; }
    const int end = lo;

    const int t = threadIdx.x;
    const int c = t & 31;
    const int sub = t >> 5;
    float acc = 0.f;
    for (int n = start + sub; n < end; n += 8) {
        float v = g_bufB[(size_t)n * 32 + c] + b2[c];
        acc += v > 0.f ? v : expm1f(v);
    }
    __shared__ float red[256];
    red[t] = acc;
    __syncthreads();
    if (sub == 0) {
        float s = 0.f;
#pragma unroll
        for (int k = 0; k < 8; k++) s += red[k * 32 + c];
        float cnt = (float)(end - start);
        g_g[blockIdx.x * 32 + c] = s / fmaxf(cnt, 1.f);
    }
}

// ---------------- final MLP: relu(g@W1+b1)@W2+b2 ----------------
__global__ __launch_bounds__(128) void k_mlp(
    const float* __restrict__ w1, const float* __restrict__ b1,
    const float* __restrict__ w2, const float* __restrict__ b2o,
    float* __restrict__ out) {
    const int gi = blockIdx.x;
    const int t = threadIdx.x;
    __shared__ float gv[32], t1[128];
    if (t < 32) gv[t] = g_g[gi * 32 + t];
    __syncthreads();
    float acc = b1[t];
#pragma unroll
    for (int c = 0; c < 32; c++) acc += gv[c] * w1[c * 128 + t];
    t1[t] = fmaxf(acc, 0.f);
    __syncthreads();
    if (t < 8) {
        float o = b2o[t];
#pragma unroll 8
        for (int j = 0; j < 128; j++) o += t1[j] * w2[j * 8 + t];
        out[gi * 8 + t] = o;
    }
}

// ---------------- launch: kernel launches ONLY ----------------
extern "C" void kernel_launch(void* const* d_in, const int* in_sizes, int n_in,
                              void* d_out, int out_size) {
    const float* x     = (const float*)d_in[0];
    const void*  ei    = d_in[1];
    const void*  batch = d_in[2];
    const float* W0  = (const float*)d_in[3];
    const float* as0 = (const float*)d_in[4];
    const float* ad0 = (const float*)d_in[5];
    const float* b0  = (const float*)d_in[6];
    const float* W1  = (const float*)d_in[7];
    const float* as1 = (const float*)d_in[8];
    const float* ad1 = (const float*)d_in[9];
    const float* b1  = (const float*)d_in[10];
    const float* W2  = (const float*)d_in[11];
    const float* as2 = (const float*)d_in[12];
    const float* ad2 = (const float*)d_in[13];
    const float* b2  = (const float*)d_in[14];
    const float* l1w = (const float*)d_in[15];
    const float* l1b = (const float*)d_in[16];
    const float* l2w = (const float*)d_in[17];
    const float* l2b = (const float*)d_in[18];

    const int eblk = (NE_TOT + 255) / 256;
    const int nblk = (N_NODES + 255) / 256;
    const int dblk = (N_EDGES + 255) / 256;
    const int gemm128_blocks = (N_NODES + 31) / 32;
    const int gemm32_blocks  = (N_NODES + 127) / 128;
    const int agg_blocks     = (N_NODES + 7) / 8;

    // dtype detect + CSR build (shared across all 3 layers)
    k_zero_deg<<<nblk, 256>>>(1);
    k_detect<<<dblk, 256>>>(ei);
    k_hist<<<eblk, 256>>>(ei);
    k_scan<<<1, 1024>>>();
    k_zero_deg<<<nblk, 256>>>(0);
    k_scatter<<<eblk, 256>>>(ei);

    // layer 0: x -> bufA, agg -> bufB
    k_gemm<128, false, 0><<<gemm128_blocks, 128>>>(x, W0, nullptr, as0, ad0);
    k_agg<4><<<agg_blocks, 256>>>();
    // layer 1: elu(bufB+b0) @ W1 -> bufA, agg -> bufB
    k_gemm<128, true, 1><<<gemm128_blocks, 128>>>(nullptr, W1, b0, as1, ad1);
    k_agg<4><<<agg_blocks, 256>>>();
    // layer 2: elu(bufB+b1) @ W2 -> bufA(32), agg -> bufB(32)
    k_gemm<32, true, 1><<<gemm32_blocks, 128>>>(nullptr, W2, b1, as2, ad2);
    k_agg<1><<<agg_blocks, 256>>>();

    // pool (fused elu+b2) + MLP
    k_pool<<<NUM_GRAPHS, 256>>>(batch, b2);
    k_mlp<<<NUM_GRAPHS, 128>>>(l1w, l1b, l2w, l2b, (float*)d_out);
}

// round 5
// speedup vs baseline: 1.0455x; 1.0455x over previous
#include <cuda_runtime.h>
#include <cstdint>

#define N_NODES 40000
#define N_EDGES 640000
#define NUM_GRAPHS 64
#define NE_TOT (N_EDGES + N_NODES)

// ---------------- device scratch (referenced directly by symbol) ----------------
__device__ float g_bufA[N_NODES * 128];     // GEMM output h
__device__ float g_bufB[N_NODES * 128];     // aggregation output / next input
__device__ float g_als[N_NODES * 4];
__device__ float g_ald[N_NODES * 4];
__device__ int   g_deg[N_NODES];            // degree, then reused as cursor
__device__ int   g_rs[N_NODES + 1];         // CSR row starts (by dst)
__device__ int   g_srcs[NE_TOT];            // CSR src list (incl. self loops)
__device__ float g_g[NUM_GRAPHS * 32];      // pooled graph features
__device__ int   g_is64;                    // 1 if edge_index/batch are int64

// ---------------- index helpers ----------------
__device__ __forceinline__ int load_idx(const void* p, int i, bool is64) {
    return is64 ? (int)((const long long*)p)[i] : ((const int*)p)[i];
}

// ---------------- dtype detection + zero ----------------
__global__ void k_detect(const void* __restrict__ ei) {
    int i = blockIdx.x * blockDim.x + threadIdx.x;
    int idx = 2 * i + 1;
    if (idx < 2 * N_EDGES) {
        if (((const int*)ei)[idx] != 0) g_is64 = 0;
    }
}

__global__ void k_zero_deg(int preset64) {
    int i = blockIdx.x * blockDim.x + threadIdx.x;
    if (i < N_NODES) g_deg[i] = 0;
    if (i == 0 && preset64) g_is64 = 1;
}

// ---------------- CSR build ----------------
__global__ void k_hist(const void* __restrict__ ei) {
    int i = blockIdx.x * blockDim.x + threadIdx.x;
    if (i >= NE_TOT) return;
    const bool is64 = (g_is64 != 0);
    int d = (i < N_EDGES) ? load_idx(ei, N_EDGES + i, is64) : (i - N_EDGES);
    if ((unsigned)d < (unsigned)N_NODES) atomicAdd(&g_deg[d], 1);
}

// register-resident scan: 40 values/thread, warp-shuffle block scan.
// Also zeroes g_deg (cursor for k_scatter).
__global__ __launch_bounds__(1024) void k_scan() {
    __shared__ int warp_sums[32];
    const int t = threadIdx.x;
    const int lane = t & 31, wid = t >> 5;
    const int base = t * 40;
    int v[40];
    int s = 0;
#pragma unroll
    for (int i = 0; i < 40; i++) {
        int idx = base + i;
        v[i] = (idx < N_NODES) ? g_deg[idx] : 0;
        s += v[i];
    }
    int x = s;
#pragma unroll
    for (int o = 1; o < 32; o <<= 1) {
        int y = __shfl_up_sync(0xffffffffu, x, o);
        if (lane >= o) x += y;
    }
    if (lane == 31) warp_sums[wid] = x;
    __syncthreads();
    if (wid == 0) {
        int ws = warp_sums[lane];
#pragma unroll
        for (int o = 1; o < 32; o <<= 1) {
            int y = __shfl_up_sync(0xffffffffu, ws, o);
            if (lane >= o) ws += y;
        }
        warp_sums[lane] = ws;
    }
    __syncthreads();
    int prefix = x - s + (wid ? warp_sums[wid - 1] : 0);   // exclusive prefix
#pragma unroll
    for (int i = 0; i < 40; i++) {
        int idx = base + i;
        if (idx < N_NODES) {
            g_rs[idx] = prefix;
            prefix += v[i];
            g_deg[idx] = 0;          // reset cursor for scatter
        }
    }
    if (t == 1023) g_rs[N_NODES] = prefix;
}

__global__ void k_scatter(const void* __restrict__ ei) {
    int i = blockIdx.x * blockDim.x + threadIdx.x;
    if (i >= NE_TOT) return;
    const bool is64 = (g_is64 != 0);
    int s, d;
    if (i < N_EDGES) {
        s = load_idx(ei, i, is64);
        d = load_idx(ei, N_EDGES + i, is64);
    } else {
        s = d = i - N_EDGES;
    }
    if ((unsigned)d >= (unsigned)N_NODES || (unsigned)s >= (unsigned)N_NODES) return;
    int pos = g_rs[d] + atomicAdd(&g_deg[d], 1);
    g_srcs[pos] = s;
}

// ---------------- big GEMM: [N,128]@[128,128] + fused ELU in, als/ald out ----
// 256 threads, block tile 64 rows x 128 cols, thread tile 8 rows x 4 cols.
// x tile in smem (warp-broadcast reads), W via LDG.128 (L1 resident).
template <bool ACT, int SRC>
__global__ __launch_bounds__(256) void k_gemm128(
    const float* __restrict__ xin, const float* __restrict__ W,
    const float* __restrict__ bprev,
    const float* __restrict__ a_src, const float* __restrict__ a_dst) {
    __shared__ float xs[64][128];
    const int t = threadIdx.x;
    const int cg = t & 31;     // col group: cols cg*4 .. cg*4+3 (warp covers all 128)
    const int rg = t >> 5;     // row group (warp id): rows rg*8 .. rg*8+7
    const int rbase = blockIdx.x * 64;   // 625 blocks * 64 = 40000 exactly
    const float* __restrict__ in = (SRC == 0) ? xin : g_bufB;
    const float4* __restrict__ src4 =
        reinterpret_cast<const float4*>(in + (size_t)rbase * 128);
    const float4* __restrict__ bp4 = reinterpret_cast<const float4*>(bprev);

    // load + activate 64x128 tile
#pragma unroll
    for (int i = 0; i < 8; i++) {
        int f = t + i * 256;           // 0..2047 float4s
        float4 v = src4[f];
        if (ACT) {
            float4 b = bp4[f & 31];
            v.x += b.x; v.y += b.y; v.z += b.z; v.w += b.w;
            v.x = v.x > 0.f ? v.x : expm1f(v.x);
            v.y = v.y > 0.f ? v.y : expm1f(v.y);
            v.z = v.z > 0.f ? v.z : expm1f(v.z);
            v.w = v.w > 0.f ? v.w : expm1f(v.w);
        }
        *reinterpret_cast<float4*>(&xs[f >> 5][(f & 31) * 4]) = v;
    }
    __syncthreads();

    float acc[8][4];
#pragma unroll
    for (int r = 0; r < 8; r++)
#pragma unroll
        for (int c = 0; c < 4; c++) acc[r][c] = 0.f;

    const float4* __restrict__ W4 = reinterpret_cast<const float4*>(W);
#pragma unroll 4
    for (int k = 0; k < 128; k++) {
        float4 w = __ldg(&W4[k * 32 + cg]);
        float xv[8];
#pragma unroll
        for (int r = 0; r < 8; r++) xv[r] = xs[rg * 8 + r][k];  // broadcast
#pragma unroll
        for (int r = 0; r < 8; r++) {
            acc[r][0] += xv[r] * w.x;
            acc[r][1] += xv[r] * w.y;
            acc[r][2] += xv[r] * w.z;
            acc[r][3] += xv[r] * w.w;
        }
    }

    // epilogue: store h + fused als/ald (reduce 8 lanes per head)
    const int head = cg >> 3;
    const float4 as4 = reinterpret_cast<const float4*>(a_src)[head * 8 + (cg & 7)];
    const float4 ad4 = reinterpret_cast<const float4*>(a_dst)[head * 8 + (cg & 7)];
#pragma unroll
    for (int r = 0; r < 8; r++) {
        const int row = rbase + rg * 8 + r;
        float4 o; o.x = acc[r][0]; o.y = acc[r][1]; o.z = acc[r][2]; o.w = acc[r][3];
        *reinterpret_cast<float4*>(&g_bufA[(size_t)row * 128 + cg * 4]) = o;
        float s1 = o.x * as4.x + o.y * as4.y + o.z * as4.z + o.w * as4.w;
        float s2 = o.x * ad4.x + o.y * ad4.y + o.z * ad4.z + o.w * ad4.w;
#pragma unroll
        for (int off = 1; off < 8; off <<= 1) {
            s1 += __shfl_xor_sync(0xffffffffu, s1, off);
            s2 += __shfl_xor_sync(0xffffffffu, s2, off);
        }
        if ((cg & 7) == 0) {
            g_als[row * 4 + head] = s1;
            g_ald[row * 4 + head] = s2;
        }
    }
}

// ---------------- small GEMM (layer 2): [N,128]@[128,32] ----------------
__global__ __launch_bounds__(128) void k_gemm32(
    const float* __restrict__ W, const float* __restrict__ bprev,
    const float* __restrict__ a_src, const float* __restrict__ a_dst) {
    constexpr int M = 32;
    constexpr int RPP = 32;
    const int t = threadIdx.x;
    const int col = t % M;
    const int grp = t / M;
    const int c = col;
    __shared__ float xs[RPP][128];
    const float asv = a_src[c];
    const float adv = a_dst[c];
    const int rowblock = blockIdx.x * (4 * RPP);

    for (int pass = 0; pass < 4; ++pass) {
        const int rbase = rowblock + pass * RPP;
        __syncthreads();
        for (int j = t; j < RPP * 128; j += 128) {
            int r = rbase + (j >> 7);
            float v = (r < N_NODES) ? g_bufB[(size_t)r * 128 + (j & 127)] : 0.f;
            v += bprev[j & 127];
            v = v > 0.f ? v : expm1f(v);
            xs[j >> 7][j & 127] = v;
        }
        __syncthreads();
        float acc[8] = {0, 0, 0, 0, 0, 0, 0, 0};
        const int r0 = grp * 8;
#pragma unroll 4
        for (int k = 0; k < 128; ++k) {
            float w = W[k * M + col];
#pragma unroll
            for (int r = 0; r < 8; ++r) acc[r] += xs[r0 + r][k] * w;
        }
#pragma unroll
        for (int r = 0; r < 8; ++r) {
            int row = rbase + r0 + r;
            if (row < N_NODES) {
                g_bufA[(size_t)row * M + col] = acc[r];
                float s1 = acc[r] * asv, s2 = acc[r] * adv;
#pragma unroll
                for (int o = 16; o; o >>= 1) {
                    s1 += __shfl_xor_sync(0xffffffffu, s1, o);
                    s2 += __shfl_xor_sync(0xffffffffu, s2, o);
                }
                if (c == 0) {
                    g_als[row] = s1;
                    g_ald[row] = s2;
                }
            }
        }
    }
}

// ---------------- GAT aggregation: one warp per dst, NO max pass ----------------
// alpha = exp(e)/sum(exp(e)) is identical to the max-shifted softmax; logits are
// O(+-15) here, clamped at 60 for safety.
template <int H>
__global__ __launch_bounds__(256) void k_agg() {
    int d = (blockIdx.x * blockDim.x + threadIdx.x) >> 5;
    if (d >= N_NODES) return;
    const int lane = threadIdx.x & 31;
    const int beg = g_rs[d], end = g_rs[d + 1];
    constexpr int CT = H * 32;
    constexpr int FPL = CT / 32;
    const int head = (H == 1) ? 0 : (lane >> 3);

    const float aldh = g_ald[d * H + head];
    float den = 0.f;
    float acc[FPL];
#pragma unroll
    for (int f = 0; f < FPL; f++) acc[f] = 0.f;

    int s_next = (beg < end) ? g_srcs[beg] : 0;
    for (int j = beg; j < end; ++j) {
        const int s = s_next;
        if (j + 1 < end) s_next = g_srcs[j + 1];
        float e = g_als[s * H + head] + aldh;
        e = e > 0.f ? e : 0.2f * e;
        e = fminf(e, 60.f);
        float p = __expf(e);
        den += p;
        const float* hr = g_bufA + (size_t)s * CT + lane * FPL;
        if (FPL == 4) {
            float4 v = *reinterpret_cast<const float4*>(hr);
            acc[0] += p * v.x; acc[1] += p * v.y;
            acc[2] += p * v.z; acc[3] += p * v.w;
        } else {
            acc[0] += p * hr[0];
        }
    }
    float inv = 1.f / fmaxf(den, 1e-16f);
    float* orow = g_bufB + (size_t)d * CT + lane * FPL;
#pragma unroll
    for (int f = 0; f < FPL; f++) orow[f] = acc[f] * inv;
}

// ---------------- global mean pool (batch sorted, fused ELU+bias) ----------------
__global__ __launch_bounds__(256) void k_pool(
    const void* __restrict__ batch, const float* __restrict__ b2) {
    const bool is64 = (g_is64 != 0);
    const int gi = blockIdx.x;
    int lo = 0, hi = N_NODES;
    while (lo < hi) { int mid = (lo + hi) >> 1;
        if (load_idx(batch, mid, is64) < gi) lo = mid + 1; else hi = mid; }
    const int start = lo;
    lo = start; hi = N_NODES;
    while (lo < hi) { int mid = (lo + hi) >> 1;
        if (load_idx(batch, mid, is64) < gi + 1) lo = mid + 1; else hi = mid; }
    const int end = lo;

    const int t = threadIdx.x;
    const int c = t & 31;
    const int sub = t >> 5;
    float acc = 0.f;
    for (int n = start + sub; n < end; n += 8) {
        float v = g_bufB[(size_t)n * 32 + c] + b2[c];
        acc += v > 0.f ? v : expm1f(v);
    }
    __shared__ float red[256];
    red[t] = acc;
    __syncthreads();
    if (sub == 0) {
        float s = 0.f;
#pragma unroll
        for (int k = 0; k < 8; k++) s += red[k * 32 + c];
        float cnt = (float)(end - start);
        g_g[blockIdx.x * 32 + c] = s / fmaxf(cnt, 1.f);
    }
}

// ---------------- final MLP: relu(g@W1+b1)@W2+b2 ----------------
__global__ __launch_bounds__(128) void k_mlp(
    const float* __restrict__ w1, const float* __restrict__ b1,
    const float* __restrict__ w2, const float* __restrict__ b2o,
    float* __restrict__ out) {
    const int gi = blockIdx.x;
    const int t = threadIdx.x;
    __shared__ float gv[32], t1[128];
    if (t < 32) gv[t] = g_g[gi * 32 + t];
    __syncthreads();
    float acc = b1[t];
#pragma unroll
    for (int c = 0; c < 32; c++) acc += gv[c] * w1[c * 128 + t];
    t1[t] = fmaxf(acc, 0.f);
    __syncthreads();
    if (t < 8) {
        float o = b2o[t];
#pragma unroll 8
        for (int j = 0; j < 128; j++) o += t1[j] * w2[j * 8 + t];
        out[gi * 8 + t] = o;
    }
}

// ---------------- launch: kernel launches ONLY ----------------
extern "C" void kernel_launch(void* const* d_in, const int* in_sizes, int n_in,
                              void* d_out, int out_size) {
    const float* x     = (const float*)d_in[0];
    const void*  ei    = d_in[1];
    const void*  batch = d_in[2];
    const float* W0  = (const float*)d_in[3];
    const float* as0 = (const float*)d_in[4];
    const float* ad0 = (const float*)d_in[5];
    const float* b0  = (const float*)d_in[6];
    const float* W1  = (const float*)d_in[7];
    const float* as1 = (const float*)d_in[8];
    const float* ad1 = (const float*)d_in[9];
    const float* b1  = (const float*)d_in[10];
    const float* W2  = (const float*)d_in[11];
    const float* as2 = (const float*)d_in[12];
    const float* ad2 = (const float*)d_in[13];
    const float* b2  = (const float*)d_in[14];
    const float* l1w = (const float*)d_in[15];
    const float* l1b = (const float*)d_in[16];
    const float* l2w = (const float*)d_in[17];
    const float* l2b = (const float*)d_in[18];

    const int eblk = (NE_TOT + 255) / 256;
    const int nblk = (N_NODES + 255) / 256;
    const int dblk = (N_EDGES + 255) / 256;
    const int gemm128_blocks = N_NODES / 64;             // 625, exact
    const int gemm32_blocks  = (N_NODES + 127) / 128;
    const int agg_blocks     = (N_NODES + 7) / 8;

    // dtype detect + CSR build (shared across all 3 layers)
    k_zero_deg<<<nblk, 256>>>(1);
    k_detect<<<dblk, 256>>>(ei);
    k_hist<<<eblk, 256>>>(ei);
    k_scan<<<1, 1024>>>();          // also zeroes deg (cursor)
    k_scatter<<<eblk, 256>>>(ei);

    // layer 0: x -> bufA, agg -> bufB
    k_gemm128<false, 0><<<gemm128_blocks, 256>>>(x, W0, nullptr, as0, ad0);
    k_agg<4><<<agg_blocks, 256>>>();
    // layer 1: elu(bufB+b0) @ W1 -> bufA, agg -> bufB
    k_gemm128<true, 1><<<gemm128_blocks, 256>>>(nullptr, W1, b0, as1, ad1);
    k_agg<4><<<agg_blocks, 256>>>();
    // layer 2: elu(bufB+b1) @ W2 -> bufA(32), agg -> bufB(32)
    k_gemm32<<<gemm32_blocks, 128>>>(W2, b1, as2, ad2);
    k_agg<1><<<agg_blocks, 256>>>();

    // pool (fused elu+b2) + MLP
    k_pool<<<NUM_GRAPHS, 256>>>(batch, b2);
    k_mlp<<<NUM_GRAPHS, 128>>>(l1w, l1b, l2w, l2b, (float*)d_out);
}

// round 6
// speedup vs baseline: 1.1664x; 1.1157x over previous
#include <cuda_runtime.h>
#include <cstdint>

#define N_NODES 40000
#define N_EDGES 640000
#define NUM_GRAPHS 64
#define NE_TOT (N_EDGES + N_NODES)
#define N_PAD 40960                 // 10 * 4096, covers N_NODES

// ---------------- device scratch (referenced directly by symbol) ----------------
__device__ float g_bufA[N_NODES * 128];     // GEMM output h
__device__ float g_bufB[N_NODES * 128];     // aggregation output / next input
__device__ float g_als[N_NODES * 4];
__device__ float g_ald[N_NODES * 4];
__device__ __align__(16) int g_deg[N_PAD];        // degree, then cursor (padded, zeroed)
__device__ __align__(16) int g_rs[N_PAD + 4];     // CSR row starts (by dst)
__device__ int   g_srcs[NE_TOT];            // CSR src list (incl. self loops)
__device__ float g_g[NUM_GRAPHS * 32];      // pooled graph features
__device__ int   g_is64;                    // 1 if edge_index/batch are int64

// ---------------- index helpers ----------------
__device__ __forceinline__ int load_idx(const void* p, int i, bool is64) {
    return is64 ? (int)((const long long*)p)[i] : ((const int*)p)[i];
}

// ---------------- dtype detection (sample first 1024 edges) ----------------
__global__ void k_detect(const void* __restrict__ ei) {
    int idx = 2 * threadIdx.x + 1;               // high word if int64
    if (((const int*)ei)[idx] != 0) g_is64 = 0;  // racing 0-stores: fine
}

__global__ void k_zero_deg(int preset64) {
    int i = blockIdx.x * blockDim.x + threadIdx.x;
    if (i < N_PAD) g_deg[i] = 0;
    if (i == 0 && preset64) g_is64 = 1;
}

// ---------------- CSR build ----------------
__global__ void k_hist(const void* __restrict__ ei) {
    int i = blockIdx.x * blockDim.x + threadIdx.x;
    if (i >= NE_TOT) return;
    const bool is64 = (g_is64 != 0);
    int d = (i < N_EDGES) ? load_idx(ei, N_EDGES + i, is64) : (i - N_EDGES);
    if ((unsigned)d < (unsigned)N_NODES) atomicAdd(&g_deg[d], 1);
}

// coalesced block scan: 10 tiles of 4096 ints, one int4 per thread per tile.
// No register arrays -> no spills. Also zeroes g_deg (cursor for k_scatter).
// Pad region [40000,40960) is zero, so g_rs[40000] lands on the exact total.
__global__ __launch_bounds__(1024) void k_scan() {
    __shared__ int wsum[32];
    const int t = threadIdx.x;
    const int lane = t & 31, wid = t >> 5;
    int4* __restrict__ deg4 = reinterpret_cast<int4*>(g_deg);
    int4* __restrict__ rs4  = reinterpret_cast<int4*>(g_rs);
    int carry = 0;
    const int4 zero4 = make_int4(0, 0, 0, 0);

#pragma unroll
    for (int it = 0; it < 10; ++it) {
        const int idx = it * 1024 + t;           // int4 index
        int4 v = deg4[idx];
        int s = v.x + v.y + v.z + v.w;
        int x = s;
#pragma unroll
        for (int o = 1; o < 32; o <<= 1) {
            int y = __shfl_up_sync(0xffffffffu, x, o);
            if (lane >= o) x += y;
        }
        if (lane == 31) wsum[wid] = x;
        __syncthreads();
        if (wid == 0) {
            int ws = wsum[lane];
#pragma unroll
            for (int o = 1; o < 32; o <<= 1) {
                int y = __shfl_up_sync(0xffffffffu, ws, o);
                if (lane >= o) ws += y;
            }
            wsum[lane] = ws;
        }
        __syncthreads();
        int excl = carry + x - s + (wid ? wsum[wid - 1] : 0);
        int4 r;
        r.x = excl;
        r.y = excl + v.x;
        r.z = r.y + v.y;
        r.w = r.z + v.z;
        rs4[idx]  = r;
        deg4[idx] = zero4;                       // reset cursor
        carry += wsum[31];
        __syncthreads();                         // protect wsum reuse
    }
    // g_rs[40000] already holds the total (pad degs are zero)
}

__global__ void k_scatter(const void* __restrict__ ei) {
    int i = blockIdx.x * blockDim.x + threadIdx.x;
    if (i >= NE_TOT) return;
    const bool is64 = (g_is64 != 0);
    int s, d;
    if (i < N_EDGES) {
        s = load_idx(ei, i, is64);
        d = load_idx(ei, N_EDGES + i, is64);
    } else {
        s = d = i - N_EDGES;
    }
    if ((unsigned)d >= (unsigned)N_NODES || (unsigned)s >= (unsigned)N_NODES) return;
    int pos = g_rs[d] + atomicAdd(&g_deg[d], 1);
    g_srcs[pos] = s;
}

// ---------------- big GEMM: [N,128]@[128,128] + fused ELU in, als/ald out ----
template <bool ACT, int SRC>
__global__ __launch_bounds__(256) void k_gemm128(
    const float* __restrict__ xin, const float* __restrict__ W,
    const float* __restrict__ bprev,
    const float* __restrict__ a_src, const float* __restrict__ a_dst) {
    __shared__ float xs[64][128];
    const int t = threadIdx.x;
    const int cg = t & 31;     // col group: cols cg*4 .. cg*4+3
    const int rg = t >> 5;     // row group (warp id): rows rg*8 .. rg*8+7
    const int rbase = blockIdx.x * 64;   // 625 blocks * 64 = 40000 exactly
    const float* __restrict__ in = (SRC == 0) ? xin : g_bufB;
    const float4* __restrict__ src4 =
        reinterpret_cast<const float4*>(in + (size_t)rbase * 128);
    const float4* __restrict__ bp4 = reinterpret_cast<const float4*>(bprev);

#pragma unroll
    for (int i = 0; i < 8; i++) {
        int f = t + i * 256;
        float4 v = src4[f];
        if (ACT) {
            float4 b = bp4[f & 31];
            v.x += b.x; v.y += b.y; v.z += b.z; v.w += b.w;
            v.x = v.x > 0.f ? v.x : expm1f(v.x);
            v.y = v.y > 0.f ? v.y : expm1f(v.y);
            v.z = v.z > 0.f ? v.z : expm1f(v.z);
            v.w = v.w > 0.f ? v.w : expm1f(v.w);
        }
        *reinterpret_cast<float4*>(&xs[f >> 5][(f & 31) * 4]) = v;
    }
    __syncthreads();

    float acc[8][4];
#pragma unroll
    for (int r = 0; r < 8; r++)
#pragma unroll
        for (int c = 0; c < 4; c++) acc[r][c] = 0.f;

    const float4* __restrict__ W4 = reinterpret_cast<const float4*>(W);
#pragma unroll 4
    for (int k = 0; k < 128; k++) {
        float4 w = __ldg(&W4[k * 32 + cg]);
        float xv[8];
#pragma unroll
        for (int r = 0; r < 8; r++) xv[r] = xs[rg * 8 + r][k];  // broadcast
#pragma unroll
        for (int r = 0; r < 8; r++) {
            acc[r][0] += xv[r] * w.x;
            acc[r][1] += xv[r] * w.y;
            acc[r][2] += xv[r] * w.z;
            acc[r][3] += xv[r] * w.w;
        }
    }

    const int head = cg >> 3;
    const float4 as4 = reinterpret_cast<const float4*>(a_src)[head * 8 + (cg & 7)];
    const float4 ad4 = reinterpret_cast<const float4*>(a_dst)[head * 8 + (cg & 7)];
#pragma unroll
    for (int r = 0; r < 8; r++) {
        const int row = rbase + rg * 8 + r;
        float4 o; o.x = acc[r][0]; o.y = acc[r][1]; o.z = acc[r][2]; o.w = acc[r][3];
        *reinterpret_cast<float4*>(&g_bufA[(size_t)row * 128 + cg * 4]) = o;
        float s1 = o.x * as4.x + o.y * as4.y + o.z * as4.z + o.w * as4.w;
        float s2 = o.x * ad4.x + o.y * ad4.y + o.z * ad4.z + o.w * ad4.w;
#pragma unroll
        for (int off = 1; off < 8; off <<= 1) {
            s1 += __shfl_xor_sync(0xffffffffu, s1, off);
            s2 += __shfl_xor_sync(0xffffffffu, s2, off);
        }
        if ((cg & 7) == 0) {
            g_als[row * 4 + head] = s1;
            g_ald[row * 4 + head] = s2;
        }
    }
}

// ---------------- small GEMM (layer 2): [N,128]@[128,32] ----------------
__global__ __launch_bounds__(128) void k_gemm32(
    const float* __restrict__ W, const float* __restrict__ bprev,
    const float* __restrict__ a_src, const float* __restrict__ a_dst) {
    constexpr int M = 32;
    constexpr int RPP = 32;
    const int t = threadIdx.x;
    const int col = t % M;
    const int grp = t / M;
    const int c = col;
    __shared__ float xs[RPP][128];
    const float asv = a_src[c];
    const float adv = a_dst[c];
    const int rowblock = blockIdx.x * (4 * RPP);

    for (int pass = 0; pass < 4; ++pass) {
        const int rbase = rowblock + pass * RPP;
        __syncthreads();
        for (int j = t; j < RPP * 128; j += 128) {
            int r = rbase + (j >> 7);
            float v = (r < N_NODES) ? g_bufB[(size_t)r * 128 + (j & 127)] : 0.f;
            v += bprev[j & 127];
            v = v > 0.f ? v : expm1f(v);
            xs[j >> 7][j & 127] = v;
        }
        __syncthreads();
        float acc[8] = {0, 0, 0, 0, 0, 0, 0, 0};
        const int r0 = grp * 8;
#pragma unroll 4
        for (int k = 0; k < 128; ++k) {
            float w = W[k * M + col];
#pragma unroll
            for (int r = 0; r < 8; ++r) acc[r] += xs[r0 + r][k] * w;
        }
#pragma unroll
        for (int r = 0; r < 8; ++r) {
            int row = rbase + r0 + r;
            if (row < N_NODES) {
                g_bufA[(size_t)row * M + col] = acc[r];
                float s1 = acc[r] * asv, s2 = acc[r] * adv;
#pragma unroll
                for (int o = 16; o; o >>= 1) {
                    s1 += __shfl_xor_sync(0xffffffffu, s1, o);
                    s2 += __shfl_xor_sync(0xffffffffu, s2, o);
                }
                if (c == 0) {
                    g_als[row] = s1;
                    g_ald[row] = s2;
                }
            }
        }
    }
}

// ---------------- GAT aggregation: one warp per dst, NO max pass ----------------
template <int H>
__global__ __launch_bounds__(256) void k_agg() {
    int d = (blockIdx.x * blockDim.x + threadIdx.x) >> 5;
    if (d >= N_NODES) return;
    const int lane = threadIdx.x & 31;
    const int beg = g_rs[d], end = g_rs[d + 1];
    constexpr int CT = H * 32;
    constexpr int FPL = CT / 32;
    const int head = (H == 1) ? 0 : (lane >> 3);

    const float aldh = g_ald[d * H + head];
    float den = 0.f;
    float acc[FPL];
#pragma unroll
    for (int f = 0; f < FPL; f++) acc[f] = 0.f;

    int s_next = (beg < end) ? g_srcs[beg] : 0;
    for (int j = beg; j < end; ++j) {
        const int s = s_next;
        if (j + 1 < end) s_next = g_srcs[j + 1];
        float e = g_als[s * H + head] + aldh;
        e = e > 0.f ? e : 0.2f * e;
        e = fminf(e, 60.f);
        float p = __expf(e);
        den += p;
        const float* hr = g_bufA + (size_t)s * CT + lane * FPL;
        if (FPL == 4) {
            float4 v = *reinterpret_cast<const float4*>(hr);
            acc[0] += p * v.x; acc[1] += p * v.y;
            acc[2] += p * v.z; acc[3] += p * v.w;
        } else {
            acc[0] += p * hr[0];
        }
    }
    float inv = 1.f / fmaxf(den, 1e-16f);
    float* orow = g_bufB + (size_t)d * CT + lane * FPL;
#pragma unroll
    for (int f = 0; f < FPL; f++) orow[f] = acc[f] * inv;
}

// ---------------- global mean pool (batch sorted, fused ELU+bias) ----------------
__global__ __launch_bounds__(256) void k_pool(
    const void* __restrict__ batch, const float* __restrict__ b2) {
    const bool is64 = (g_is64 != 0);
    const int gi = blockIdx.x;
    int lo = 0, hi = N_NODES;
    while (lo < hi) { int mid = (lo + hi) >> 1;
        if (load_idx(batch, mid, is64) < gi) lo = mid + 1; else hi = mid; }
    const int start = lo;
    lo = start; hi = N_NODES;
    while (lo < hi) { int mid = (lo + hi) >> 1;
        if (load_idx(batch, mid, is64) < gi + 1) lo = mid + 1; else hi = mid; }
    const int end = lo;

    const int t = threadIdx.x;
    const int c = t & 31;
    const int sub = t >> 5;
    float acc = 0.f;
    for (int n = start + sub; n < end; n += 8) {
        float v = g_bufB[(size_t)n * 32 + c] + b2[c];
        acc += v > 0.f ? v : expm1f(v);
    }
    __shared__ float red[256];
    red[t] = acc;
    __syncthreads();
    if (sub == 0) {
        float s = 0.f;
#pragma unroll
        for (int k = 0; k < 8; k++) s += red[k * 32 + c];
        float cnt = (float)(end - start);
        g_g[blockIdx.x * 32 + c] = s / fmaxf(cnt, 1.f);
    }
}

// ---------------- final MLP: relu(g@W1+b1)@W2+b2 ----------------
__global__ __launch_bounds__(128) void k_mlp(
    const float* __restrict__ w1, const float* __restrict__ b1,
    const float* __restrict__ w2, const float* __restrict__ b2o,
    float* __restrict__ out) {
    const int gi = blockIdx.x;
    const int t = threadIdx.x;
    __shared__ float gv[32], t1[128];
    if (t < 32) gv[t] = g_g[gi * 32 + t];
    __syncthreads();
    float acc = b1[t];
#pragma unroll
    for (int c = 0; c < 32; c++) acc += gv[c] * w1[c * 128 + t];
    t1[t] = fmaxf(acc, 0.f);
    __syncthreads();
    if (t < 8) {
        float o = b2o[t];
#pragma unroll 8
        for (int j = 0; j < 128; j++) o += t1[j] * w2[j * 8 + t];
        out[gi * 8 + t] = o;
    }
}

// ---------------- launch: kernel launches ONLY ----------------
extern "C" void kernel_launch(void* const* d_in, const int* in_sizes, int n_in,
                              void* d_out, int out_size) {
    const float* x     = (const float*)d_in[0];
    const void*  ei    = d_in[1];
    const void*  batch = d_in[2];
    const float* W0  = (const float*)d_in[3];
    const float* as0 = (const float*)d_in[4];
    const float* ad0 = (const float*)d_in[5];
    const float* b0  = (const float*)d_in[6];
    const float* W1  = (const float*)d_in[7];
    const float* as1 = (const float*)d_in[8];
    const float* ad1 = (const float*)d_in[9];
    const float* b1  = (const float*)d_in[10];
    const float* W2  = (const float*)d_in[11];
    const float* as2 = (const float*)d_in[12];
    const float* ad2 = (const float*)d_in[13];
    const float* b2  = (const float*)d_in[14];
    const float* l1w = (const float*)d_in[15];
    const float* l1b = (const float*)d_in[16];
    const float* l2w = (const float*)d_in[17];
    const float* l2b = (const float*)d_in[18];

    const int eblk = (NE_TOT + 255) / 256;
    const int nblk = (N_PAD + 255) / 256;
    const int gemm128_blocks = N_NODES / 64;             // 625, exact
    const int gemm32_blocks  = (N_NODES + 127) / 128;
    const int agg_blocks     = (N_NODES + 7) / 8;

    // dtype detect + CSR build (shared across all 3 layers)
    k_zero_deg<<<nblk, 256>>>(1);
    k_detect<<<1, 1024>>>(ei);
    k_hist<<<eblk, 256>>>(ei);
    k_scan<<<1, 1024>>>();          // also zeroes deg (cursor)
    k_scatter<<<eblk, 256>>>(ei);

    // layer 0: x -> bufA, agg -> bufB
    k_gemm128<false, 0><<<gemm128_blocks, 256>>>(x, W0, nullptr, as0, ad0);
    k_agg<4><<<agg_blocks, 256>>>();
    // layer 1: elu(bufB+b0) @ W1 -> bufA, agg -> bufB
    k_gemm128<true, 1><<<gemm128_blocks, 256>>>(nullptr, W1, b0, as1, ad1);
    k_agg<4><<<agg_blocks, 256>>>();
    // layer 2: elu(bufB+b1) @ W2 -> bufA(32), agg -> bufB(32)
    k_gemm32<<<gemm32_blocks, 128>>>(W2, b1, as2, ad2);
    k_agg<1><<<agg_blocks, 256>>>();

    // pool (fused elu+b2) + MLP
    k_pool<<<NUM_GRAPHS, 256>>>(batch, b2);
    k_mlp<<<NUM_GRAPHS, 128>>>(l1w, l1b, l2w, l2b, (float*)d_out);
}

// round 7
// speedup vs baseline: 1.3088x; 1.1221x over previous
#include <cuda_runtime.h>
#include <cuda_fp16.h>
#include <cstdint>

#define N_NODES 40000
#define N_EDGES 640000
#define NUM_GRAPHS 64
#define NE_TOT (N_EDGES + N_NODES)
#define N_PAD 40960                 // 10 * 4096, covers N_NODES

// ---------------- device scratch (referenced directly by symbol) ----------------
__device__ __half  g_bufH[N_NODES * 128];   // fp16 h for 128-wide layers (agg gather)
__device__ float g_bufA[N_NODES * 32];      // fp32 h for layer 2 (32-wide)
__device__ float g_bufB[N_NODES * 128];     // aggregation output / next input
__device__ float g_als[N_NODES * 4];
__device__ float g_ald[N_NODES * 4];
__device__ __align__(16) int g_deg[N_PAD];      // degree, then cursor (padded, zeroed)
__device__ __align__(16) int g_rs[N_PAD + 4];   // CSR row starts (by dst)
__device__ int   g_srcs[NE_TOT];            // CSR src list (incl. self loops)
__device__ float g_g[NUM_GRAPHS * 32];      // pooled graph features
__device__ int   g_is64;                    // 1 if edge_index/batch are int64

// ---------------- index helpers ----------------
__device__ __forceinline__ int load_idx(const void* p, int i, bool is64) {
    return is64 ? (int)((const long long*)p)[i] : ((const int*)p)[i];
}

// ---------------- dtype detection (sample first 1024 edges) ----------------
__global__ void k_detect(const void* __restrict__ ei) {
    int idx = 2 * threadIdx.x + 1;               // high word if int64
    if (((const int*)ei)[idx] != 0) g_is64 = 0;  // racing 0-stores: fine
}

__global__ void k_zero_deg(int preset64) {
    int i = blockIdx.x * blockDim.x + threadIdx.x;
    if (i < N_PAD) g_deg[i] = 0;
    if (i == 0 && preset64) g_is64 = 1;
}

// ---------------- CSR build ----------------
__global__ void k_hist(const void* __restrict__ ei) {
    int i = blockIdx.x * blockDim.x + threadIdx.x;
    if (i >= NE_TOT) return;
    const bool is64 = (g_is64 != 0);
    int d = (i < N_EDGES) ? load_idx(ei, N_EDGES + i, is64) : (i - N_EDGES);
    if ((unsigned)d < (unsigned)N_NODES) atomicAdd(&g_deg[d], 1);
}

// pipelined block scan: 5 tiles of 8192 ints, 2x int4 per thread per tile,
// next tile prefetched before the barrier chain. Also zeroes g_deg.
__global__ __launch_bounds__(1024) void k_scan() {
    __shared__ int wsum[32];
    const int t = threadIdx.x;
    const int lane = t & 31, wid = t >> 5;
    int4* __restrict__ deg4 = reinterpret_cast<int4*>(g_deg);
    int4* __restrict__ rs4  = reinterpret_cast<int4*>(g_rs);
    int carry = 0;
    const int4 zero4 = make_int4(0, 0, 0, 0);

    int4 a = deg4[t * 2];
    int4 b = deg4[t * 2 + 1];
#pragma unroll
    for (int it = 0; it < 5; ++it) {
        int4 an, bn;
        if (it < 4) {                       // prefetch next tile
            an = deg4[(it + 1) * 2048 + t * 2];
            bn = deg4[(it + 1) * 2048 + t * 2 + 1];
        }
        int s = a.x + a.y + a.z + a.w + b.x + b.y + b.z + b.w;
        int x = s;
#pragma unroll
        for (int o = 1; o < 32; o <<= 1) {
            int y = __shfl_up_sync(0xffffffffu, x, o);
            if (lane >= o) x += y;
        }
        if (lane == 31) wsum[wid] = x;
        __syncthreads();
        if (wid == 0) {
            int ws = wsum[lane];
#pragma unroll
            for (int o = 1; o < 32; o <<= 1) {
                int y = __shfl_up_sync(0xffffffffu, ws, o);
                if (lane >= o) ws += y;
            }
            wsum[lane] = ws;
        }
        __syncthreads();
        int excl = carry + x - s + (wid ? wsum[wid - 1] : 0);
        const int idx = it * 2048 + t * 2;
        int4 r0, r1;
        r0.x = excl;        r0.y = r0.x + a.x;
        r0.z = r0.y + a.y;  r0.w = r0.z + a.z;
        r1.x = r0.w + a.w;  r1.y = r1.x + b.x;
        r1.z = r1.y + b.y;  r1.w = r1.z + b.z;
        rs4[idx]     = r0;
        rs4[idx + 1] = r1;
        deg4[idx]     = zero4;              // reset cursor
        deg4[idx + 1] = zero4;
        carry += wsum[31];
        a = an; b = bn;
        __syncthreads();                    // protect wsum reuse
    }
    // g_rs[40000] holds the exact total (pad degs are zero)
}

__global__ void k_scatter(const void* __restrict__ ei) {
    int i = blockIdx.x * blockDim.x + threadIdx.x;
    if (i >= NE_TOT) return;
    const bool is64 = (g_is64 != 0);
    int s, d;
    if (i < N_EDGES) {
        s = load_idx(ei, i, is64);
        d = load_idx(ei, N_EDGES + i, is64);
    } else {
        s = d = i - N_EDGES;
    }
    if ((unsigned)d >= (unsigned)N_NODES || (unsigned)s >= (unsigned)N_NODES) return;
    int pos = g_rs[d] + atomicAdd(&g_deg[d], 1);
    g_srcs[pos] = s;
}

// ---------------- big GEMM: [N,128]@[128,128], fp16 h out + fp32 als/ald ----
template <bool ACT, int SRC>
__global__ __launch_bounds__(256) void k_gemm128(
    const float* __restrict__ xin, const float* __restrict__ W,
    const float* __restrict__ bprev,
    const float* __restrict__ a_src, const float* __restrict__ a_dst) {
    __shared__ float xs[64][128];
    const int t = threadIdx.x;
    const int cg = t & 31;     // col group: cols cg*4 .. cg*4+3
    const int rg = t >> 5;     // row group (warp id): rows rg*8 .. rg*8+7
    const int rbase = blockIdx.x * 64;   // 625 blocks * 64 = 40000 exactly
    const float* __restrict__ in = (SRC == 0) ? xin : g_bufB;
    const float4* __restrict__ src4 =
        reinterpret_cast<const float4*>(in + (size_t)rbase * 128);
    const float4* __restrict__ bp4 = reinterpret_cast<const float4*>(bprev);

#pragma unroll
    for (int i = 0; i < 8; i++) {
        int f = t + i * 256;
        float4 v = src4[f];
        if (ACT) {
            float4 b = bp4[f & 31];
            v.x += b.x; v.y += b.y; v.z += b.z; v.w += b.w;
            v.x = v.x > 0.f ? v.x : expm1f(v.x);
            v.y = v.y > 0.f ? v.y : expm1f(v.y);
            v.z = v.z > 0.f ? v.z : expm1f(v.z);
            v.w = v.w > 0.f ? v.w : expm1f(v.w);
        }
        *reinterpret_cast<float4*>(&xs[f >> 5][(f & 31) * 4]) = v;
    }
    __syncthreads();

    float acc[8][4];
#pragma unroll
    for (int r = 0; r < 8; r++)
#pragma unroll
        for (int c = 0; c < 4; c++) acc[r][c] = 0.f;

    const float4* __restrict__ W4 = reinterpret_cast<const float4*>(W);
#pragma unroll 4
    for (int k = 0; k < 128; k++) {
        float4 w = __ldg(&W4[k * 32 + cg]);
        float xv[8];
#pragma unroll
        for (int r = 0; r < 8; r++) xv[r] = xs[rg * 8 + r][k];  // broadcast
#pragma unroll
        for (int r = 0; r < 8; r++) {
            acc[r][0] += xv[r] * w.x;
            acc[r][1] += xv[r] * w.y;
            acc[r][2] += xv[r] * w.z;
            acc[r][3] += xv[r] * w.w;
        }
    }

    const int head = cg >> 3;
    const float4 as4 = reinterpret_cast<const float4*>(a_src)[head * 8 + (cg & 7)];
    const float4 ad4 = reinterpret_cast<const float4*>(a_dst)[head * 8 + (cg & 7)];
#pragma unroll
    for (int r = 0; r < 8; r++) {
        const int row = rbase + rg * 8 + r;
        float4 o; o.x = acc[r][0]; o.y = acc[r][1]; o.z = acc[r][2]; o.w = acc[r][3];
        // fp16 h store (8B per thread)
        __half2 h01 = __floats2half2_rn(o.x, o.y);
        __half2 h23 = __floats2half2_rn(o.z, o.w);
        __half2* hp = reinterpret_cast<__half2*>(&g_bufH[(size_t)row * 128 + cg * 4]);
        uint2 packed;
        packed.x = *reinterpret_cast<uint32_t*>(&h01);
        packed.y = *reinterpret_cast<uint32_t*>(&h23);
        *reinterpret_cast<uint2*>(hp) = packed;
        // fused als/ald from fp32 accumulators
        float s1 = o.x * as4.x + o.y * as4.y + o.z * as4.z + o.w * as4.w;
        float s2 = o.x * ad4.x + o.y * ad4.y + o.z * ad4.z + o.w * ad4.w;
#pragma unroll
        for (int off = 1; off < 8; off <<= 1) {
            s1 += __shfl_xor_sync(0xffffffffu, s1, off);
            s2 += __shfl_xor_sync(0xffffffffu, s2, off);
        }
        if ((cg & 7) == 0) {
            g_als[row * 4 + head] = s1;
            g_ald[row * 4 + head] = s2;
        }
    }
}

// ---------------- small GEMM (layer 2): [N,128]@[128,32], fp32 h ----------------
__global__ __launch_bounds__(128) void k_gemm32(
    const float* __restrict__ W, const float* __restrict__ bprev,
    const float* __restrict__ a_src, const float* __restrict__ a_dst) {
    constexpr int M = 32;
    constexpr int RPP = 32;
    const int t = threadIdx.x;
    const int col = t % M;
    const int grp = t / M;
    __shared__ float xs[RPP][128];
    const float asv = a_src[col];
    const float adv = a_dst[col];
    const int rowblock = blockIdx.x * (4 * RPP);

    for (int pass = 0; pass < 4; ++pass) {
        const int rbase = rowblock + pass * RPP;
        __syncthreads();
        for (int j = t; j < RPP * 128; j += 128) {
            int r = rbase + (j >> 7);
            float v = (r < N_NODES) ? g_bufB[(size_t)r * 128 + (j & 127)] : 0.f;
            v += bprev[j & 127];
            v = v > 0.f ? v : expm1f(v);
            xs[j >> 7][j & 127] = v;
        }
        __syncthreads();
        float acc[8] = {0, 0, 0, 0, 0, 0, 0, 0};
        const int r0 = grp * 8;
#pragma unroll 4
        for (int k = 0; k < 128; ++k) {
            float w = W[k * M + col];
#pragma unroll
            for (int r = 0; r < 8; ++r) acc[r] += xs[r0 + r][k] * w;
        }
#pragma unroll
        for (int r = 0; r < 8; ++r) {
            int row = rbase + r0 + r;
            if (row < N_NODES) {
                g_bufA[(size_t)row * M + col] = acc[r];
                float s1 = acc[r] * asv, s2 = acc[r] * adv;
#pragma unroll
                for (int o = 16; o; o >>= 1) {
                    s1 += __shfl_xor_sync(0xffffffffu, s1, o);
                    s2 += __shfl_xor_sync(0xffffffffu, s2, o);
                }
                if (col == 0) {
                    g_als[row] = s1;
                    g_ald[row] = s2;
                }
            }
        }
    }
}

// ---------------- GAT aggregation (H=4, fp16 h): one warp per dst ----------------
__global__ __launch_bounds__(256) void k_agg4() {
    int d = (blockIdx.x * blockDim.x + threadIdx.x) >> 5;
    if (d >= N_NODES) return;
    const int lane = threadIdx.x & 31;
    const int beg = g_rs[d], end = g_rs[d + 1];
    const int head = lane >> 3;

    const float aldh = g_ald[d * 4 + head];
    float den = 0.f;
    float acc0 = 0.f, acc1 = 0.f, acc2 = 0.f, acc3 = 0.f;

    int s_next = (beg < end) ? g_srcs[beg] : 0;
    for (int j = beg; j < end; ++j) {
        const int s = s_next;
        if (j + 1 < end) s_next = g_srcs[j + 1];
        float e = g_als[s * 4 + head] + aldh;
        e = e > 0.f ? e : 0.2f * e;
        e = fminf(e, 60.f);
        float p = __expf(e);
        den += p;
        uint2 raw = *reinterpret_cast<const uint2*>(&g_bufH[(size_t)s * 128 + lane * 4]);
        __half2 h01 = *reinterpret_cast<__half2*>(&raw.x);
        __half2 h23 = *reinterpret_cast<__half2*>(&raw.y);
        float2 f01 = __half22float2(h01);
        float2 f23 = __half22float2(h23);
        acc0 += p * f01.x; acc1 += p * f01.y;
        acc2 += p * f23.x; acc3 += p * f23.y;
    }
    float inv = 1.f / fmaxf(den, 1e-16f);
    float4 o; o.x = acc0 * inv; o.y = acc1 * inv; o.z = acc2 * inv; o.w = acc3 * inv;
    *reinterpret_cast<float4*>(&g_bufB[(size_t)d * 128 + lane * 4]) = o;
}

// ---------------- GAT aggregation (H=1, fp32 h, 32 channels) ----------------
__global__ __launch_bounds__(256) void k_agg1() {
    int d = (blockIdx.x * blockDim.x + threadIdx.x) >> 5;
    if (d >= N_NODES) return;
    const int lane = threadIdx.x & 31;
    const int beg = g_rs[d], end = g_rs[d + 1];

    const float aldh = g_ald[d];
    float den = 0.f, acc = 0.f;

    int s_next = (beg < end) ? g_srcs[beg] : 0;
    for (int j = beg; j < end; ++j) {
        const int s = s_next;
        if (j + 1 < end) s_next = g_srcs[j + 1];
        float e = g_als[s] + aldh;
        e = e > 0.f ? e : 0.2f * e;
        e = fminf(e, 60.f);
        float p = __expf(e);
        den += p;
        acc += p * g_bufA[(size_t)s * 32 + lane];
    }
    g_bufB[(size_t)d * 32 + lane] = acc / fmaxf(den, 1e-16f);
}

// ---------------- global mean pool (batch sorted, fused ELU+bias) ----------------
__global__ __launch_bounds__(256) void k_pool(
    const void* __restrict__ batch, const float* __restrict__ b2) {
    const bool is64 = (g_is64 != 0);
    const int gi = blockIdx.x;
    int lo = 0, hi = N_NODES;
    while (lo < hi) { int mid = (lo + hi) >> 1;
        if (load_idx(batch, mid, is64) < gi) lo = mid + 1; else hi = mid; }
    const int start = lo;
    lo = start; hi = N_NODES;
    while (lo < hi) { int mid = (lo + hi) >> 1;
        if (load_idx(batch, mid, is64) < gi + 1) lo = mid + 1; else hi = mid; }
    const int end = lo;

    const int t = threadIdx.x;
    const int c = t & 31;
    const int sub = t >> 5;
    float acc = 0.f;
    for (int n = start + sub; n < end; n += 8) {
        float v = g_bufB[(size_t)n * 32 + c] + b2[c];
        acc += v > 0.f ? v : expm1f(v);
    }
    __shared__ float red[256];
    red[t] = acc;
    __syncthreads();
    if (sub == 0) {
        float s = 0.f;
#pragma unroll
        for (int k = 0; k < 8; k++) s += red[k * 32 + c];
        float cnt = (float)(end - start);
        g_g[blockIdx.x * 32 + c] = s / fmaxf(cnt, 1.f);
    }
}

// ---------------- final MLP: relu(g@W1+b1)@W2+b2 ----------------
__global__ __launch_bounds__(128) void k_mlp(
    const float* __restrict__ w1, const float* __restrict__ b1,
    const float* __restrict__ w2, const float* __restrict__ b2o,
    float* __restrict__ out) {
    const int gi = blockIdx.x;
    const int t = threadIdx.x;
    __shared__ float gv[32], t1[128];
    if (t < 32) gv[t] = g_g[gi * 32 + t];
    __syncthreads();
    float acc = b1[t];
#pragma unroll
    for (int c = 0; c < 32; c++) acc += gv[c] * w1[c * 128 + t];
    t1[t] = fmaxf(acc, 0.f);
    __syncthreads();
    if (t < 8) {
        float o = b2o[t];
#pragma unroll 8
        for (int j = 0; j < 128; j++) o += t1[j] * w2[j * 8 + t];
        out[gi * 8 + t] = o;
    }
}

// ---------------- launch ----------------
extern "C" void kernel_launch(void* const* d_in, const int* in_sizes, int n_in,
                              void* d_out, int out_size) {
    const float* x     = (const float*)d_in[0];
    const void*  ei    = d_in[1];
    const void*  batch = d_in[2];
    const float* W0  = (const float*)d_in[3];
    const float* as0 = (const float*)d_in[4];
    const float* ad0 = (const float*)d_in[5];
    const float* b0  = (const float*)d_in[6];
    const float* W1  = (const float*)d_in[7];
    const float* as1 = (const float*)d_in[8];
    const float* ad1 = (const float*)d_in[9];
    const float* b1  = (const float*)d_in[10];
    const float* W2  = (const float*)d_in[11];
    const float* as2 = (const float*)d_in[12];
    const float* ad2 = (const float*)d_in[13];
    const float* b2  = (const float*)d_in[14];
    const float* l1w = (const float*)d_in[15];
    const float* l1b = (const float*)d_in[16];
    const float* l2w = (const float*)d_in[17];
    const float* l2b = (const float*)d_in[18];

    const int eblk = (NE_TOT + 255) / 256;
    const int nblk = (N_PAD + 255) / 256;
    const int gemm128_blocks = N_NODES / 64;             // 625, exact
    const int gemm32_blocks  = (N_NODES + 127) / 128;
    const int agg_blocks     = (N_NODES + 7) / 8;

    // fork-join resources, created once on the (uncaptured) correctness call
    static cudaStream_t s2 = nullptr;
    static cudaEvent_t evFork = nullptr, evJoin = nullptr;
    if (s2 == nullptr) {
        cudaStreamCreateWithFlags(&s2, cudaStreamNonBlocking);
        cudaEventCreateWithFlags(&evFork, cudaEventDisableTiming);
        cudaEventCreateWithFlags(&evJoin, cudaEventDisableTiming);
    }

    // fork: CSR build on s2, GEMM0 on main stream — independent until agg0
    cudaEventRecord(evFork, 0);
    cudaStreamWaitEvent(s2, evFork, 0);

    k_zero_deg<<<nblk, 256, 0, s2>>>(1);
    k_detect<<<1, 1024, 0, s2>>>(ei);
    k_hist<<<eblk, 256, 0, s2>>>(ei);
    k_scan<<<1, 1024, 0, s2>>>();          // also zeroes deg (cursor)
    k_scatter<<<eblk, 256, 0, s2>>>(ei);
    cudaEventRecord(evJoin, s2);

    // layer 0 GEMM overlaps the CSR build
    k_gemm128<false, 0><<<gemm128_blocks, 256>>>(x, W0, nullptr, as0, ad0);

    cudaStreamWaitEvent(0, evJoin, 0);     // join before first aggregation

    k_agg4<<<agg_blocks, 256>>>();
    // layer 1: elu(bufB+b0) @ W1 -> bufH, agg -> bufB
    k_gemm128<true, 1><<<gemm128_blocks, 256>>>(nullptr, W1, b0, as1, ad1);
    k_agg4<<<agg_blocks, 256>>>();
    // layer 2: elu(bufB+b1) @ W2 -> bufA(32), agg -> bufB(32)
    k_gemm32<<<gemm32_blocks, 128>>>(W2, b1, as2, ad2);
    k_agg1<<<agg_blocks, 256>>>();

    // pool (fused elu+b2) + MLP
    k_pool<<<NUM_GRAPHS, 256>>>(batch, b2);
    k_mlp<<<NUM_GRAPHS, 128>>>(l1w, l1b, l2w, l2b, (float*)d_out);
}

// round 8
// speedup vs baseline: 1.4164x; 1.0822x over previous
#include <cuda_runtime.h>
#include <cuda_fp16.h>
#include <mma.h>
#include <cstdint>

using namespace nvcuda;

#define N_NODES 40000
#define N_EDGES 640000
#define NUM_GRAPHS 64
#define NE_TOT (N_EDGES + N_NODES)
#define N_PAD 40960                 // 10 * 4096, covers N_NODES

// ---------------- device scratch (referenced directly by symbol) ----------------
__device__ __half  g_bufH[N_NODES * 128];   // fp16 h for 128-wide layers (agg gather)
__device__ float g_bufA[N_NODES * 32];      // fp32 h for layer 2 (32-wide)
__device__ float g_bufB[N_NODES * 128];     // aggregation output / next input
__device__ float g_als[N_NODES * 4];
__device__ float g_ald[N_NODES * 4];
__device__ __align__(16) int g_deg[N_PAD];      // degree, then cursor (padded, zeroed)
__device__ __align__(16) int g_rs[N_PAD + 4];   // CSR row starts (by dst)
__device__ int   g_srcs[NE_TOT];            // CSR src list (incl. self loops)
__device__ float g_g[NUM_GRAPHS * 32];      // pooled graph features
__device__ int   g_is64;                    // 1 if edge_index/batch are int64
__device__ int   g_bsum[16];                // per-block scan totals

// ---------------- index helpers ----------------
__device__ __forceinline__ int load_idx(const void* p, int i, bool is64) {
    return is64 ? (int)((const long long*)p)[i] : ((const int*)p)[i];
}

// ---------------- dtype detection (sample first 1024 edges) ----------------
__global__ void k_detect(const void* __restrict__ ei) {
    int idx = 2 * threadIdx.x + 1;               // high word if int64
    if (((const int*)ei)[idx] != 0) g_is64 = 0;  // racing 0-stores: fine
}

__global__ void k_zero_deg(int preset64) {
    int i = blockIdx.x * blockDim.x + threadIdx.x;
    if (i < N_PAD) g_deg[i] = 0;
    if (i == 0 && preset64) g_is64 = 1;
}

// ---------------- CSR build ----------------
__global__ void k_hist(const void* __restrict__ ei) {
    int i = blockIdx.x * blockDim.x + threadIdx.x;
    if (i >= NE_TOT) return;
    const bool is64 = (g_is64 != 0);
    int d = (i < N_EDGES) ? load_idx(ei, N_EDGES + i, is64) : (i - N_EDGES);
    if ((unsigned)d < (unsigned)N_NODES) atomicAdd(&g_deg[d], 1);
}

// phase 1: 10 blocks, each scans 4096 ints locally; writes local exclusive
// prefixes to g_rs, block total to g_bsum, zeroes g_deg (cursor).
__global__ __launch_bounds__(1024) void k_scan1() {
    __shared__ int wsum[32];
    const int t = threadIdx.x;
    const int lane = t & 31, wid = t >> 5;
    const int idx = blockIdx.x * 1024 + t;        // int4 index
    int4* __restrict__ deg4 = reinterpret_cast<int4*>(g_deg);
    int4* __restrict__ rs4  = reinterpret_cast<int4*>(g_rs);

    int4 v = deg4[idx];
    int s = v.x + v.y + v.z + v.w;
    int x = s;
#pragma unroll
    for (int o = 1; o < 32; o <<= 1) {
        int y = __shfl_up_sync(0xffffffffu, x, o);
        if (lane >= o) x += y;
    }
    if (lane == 31) wsum[wid] = x;
    __syncthreads();
    if (wid == 0) {
        int ws = wsum[lane];
#pragma unroll
        for (int o = 1; o < 32; o <<= 1) {
            int y = __shfl_up_sync(0xffffffffu, ws, o);
            if (lane >= o) ws += y;
        }
        wsum[lane] = ws;
    }
    __syncthreads();
    int excl = x - s + (wid ? wsum[wid - 1] : 0);
    int4 r;
    r.x = excl;       r.y = r.x + v.x;
    r.z = r.y + v.y;  r.w = r.z + v.z;
    rs4[idx] = r;
    deg4[idx] = make_int4(0, 0, 0, 0);
    if (t == 1023) g_bsum[blockIdx.x] = wsum[31];
}

// phase 2: add block-prefix offsets. 10 blocks x 1024 int4.
__global__ __launch_bounds__(1024) void k_scan2() {
    const int b = blockIdx.x;
    if (b == 0) return;
    int off = 0;
#pragma unroll 4
    for (int i = 0; i < b; i++) off += g_bsum[i];
    const int idx = b * 1024 + threadIdx.x;
    int4* __restrict__ rs4 = reinterpret_cast<int4*>(g_rs);
    int4 r = rs4[idx];
    r.x += off; r.y += off; r.z += off; r.w += off;
    rs4[idx] = r;
}

__global__ void k_scatter(const void* __restrict__ ei) {
    int i = blockIdx.x * blockDim.x + threadIdx.x;
    if (i >= NE_TOT) return;
    const bool is64 = (g_is64 != 0);
    int s, d;
    if (i < N_EDGES) {
        s = load_idx(ei, i, is64);
        d = load_idx(ei, N_EDGES + i, is64);
    } else {
        s = d = i - N_EDGES;
    }
    if ((unsigned)d >= (unsigned)N_NODES || (unsigned)s >= (unsigned)N_NODES) return;
    int pos = g_rs[d] + atomicAdd(&g_deg[d], 1);
    g_srcs[pos] = s;
}

// ---------------- big GEMM via HMMA: [N,128]@[128,128] ----------------
// fp16 inputs in smem, fp32 accumulate, fp16 h out + fp32 als/ald.
template <bool ACT, int SRC>
__global__ __launch_bounds__(256) void k_gemm128_tc(
    const float* __restrict__ xin, const float* __restrict__ W,
    const float* __restrict__ bprev,
    const float* __restrict__ a_src, const float* __restrict__ a_dst) {
    __shared__ __align__(16) char smraw[49152];
    __half* sA = reinterpret_cast<__half*>(smraw);            // [64][128]
    __half* sB = reinterpret_cast<__half*>(smraw + 16384);    // [128][128]
    float*  stg = reinterpret_cast<float*>(smraw);            // [64][128], aliases

    const int t = threadIdx.x;
    const int rbase = blockIdx.x * 64;   // 625 blocks * 64 = 40000 exactly
    const float* __restrict__ in = (SRC == 0) ? xin : g_bufB;
    const float4* __restrict__ src4 =
        reinterpret_cast<const float4*>(in + (size_t)rbase * 128);
    const float4* __restrict__ bp4 = reinterpret_cast<const float4*>(bprev);

    // x tile (+ELU) -> fp16 smem
#pragma unroll
    for (int i = 0; i < 8; i++) {
        int f = t + i * 256;               // 2048 float4s
        float4 v = src4[f];
        if (ACT) {
            float4 b = bp4[f & 31];
            v.x += b.x; v.y += b.y; v.z += b.z; v.w += b.w;
            v.x = v.x > 0.f ? v.x : expm1f(v.x);
            v.y = v.y > 0.f ? v.y : expm1f(v.y);
            v.z = v.z > 0.f ? v.z : expm1f(v.z);
            v.w = v.w > 0.f ? v.w : expm1f(v.w);
        }
        __half2 h01 = __floats2half2_rn(v.x, v.y);
        __half2 h23 = __floats2half2_rn(v.z, v.w);
        uint2 pk;
        pk.x = *reinterpret_cast<uint32_t*>(&h01);
        pk.y = *reinterpret_cast<uint32_t*>(&h23);
        *reinterpret_cast<uint2*>(sA + f * 4) = pk;
    }
    // W -> fp16 smem
    const float4* __restrict__ W4 = reinterpret_cast<const float4*>(W);
#pragma unroll
    for (int i = 0; i < 16; i++) {
        int f = t + i * 256;               // 4096 float4s
        float4 v = W4[f];
        __half2 h01 = __floats2half2_rn(v.x, v.y);
        __half2 h23 = __floats2half2_rn(v.z, v.w);
        uint2 pk;
        pk.x = *reinterpret_cast<uint32_t*>(&h01);
        pk.y = *reinterpret_cast<uint32_t*>(&h23);
        *reinterpret_cast<uint2*>(sB + f * 4) = pk;
    }
    __syncthreads();

    const int w = t >> 5;
    const int wr = (w >> 2) * 32;          // 0 or 32
    const int wc = (w & 3) * 32;           // 0,32,64,96

    wmma::fragment<wmma::accumulator, 16, 16, 16, float> acc[2][2];
#pragma unroll
    for (int i = 0; i < 2; i++)
#pragma unroll
        for (int j = 0; j < 2; j++) wmma::fill_fragment(acc[i][j], 0.f);

    wmma::fragment<wmma::matrix_a, 16, 16, 16, __half, wmma::row_major> af[2];
    wmma::fragment<wmma::matrix_b, 16, 16, 16, __half, wmma::row_major> bf[2];
#pragma unroll
    for (int k = 0; k < 8; k++) {
        wmma::load_matrix_sync(af[0], sA + (wr +  0) * 128 + k * 16, 128);
        wmma::load_matrix_sync(af[1], sA + (wr + 16) * 128 + k * 16, 128);
        wmma::load_matrix_sync(bf[0], sB + (k * 16) * 128 + wc +  0, 128);
        wmma::load_matrix_sync(bf[1], sB + (k * 16) * 128 + wc + 16, 128);
#pragma unroll
        for (int i = 0; i < 2; i++)
#pragma unroll
            for (int j = 0; j < 2; j++)
                wmma::mma_sync(acc[i][j], af[i], bf[j], acc[i][j]);
    }
    __syncthreads();   // everyone done reading sA/sB; safe to alias as stg
#pragma unroll
    for (int i = 0; i < 2; i++)
#pragma unroll
        for (int j = 0; j < 2; j++)
            wmma::store_matrix_sync(stg + (wr + i * 16) * 128 + wc + j * 16,
                                    acc[i][j], 128, wmma::mem_row_major);
    __syncthreads();

    // epilogue: fp16 h store + fused als/ald
    const int cg = t & 31;
    const int rg = t >> 5;
    const int head = cg >> 3;
    const float4 as4 = reinterpret_cast<const float4*>(a_src)[head * 8 + (cg & 7)];
    const float4 ad4 = reinterpret_cast<const float4*>(a_dst)[head * 8 + (cg & 7)];
#pragma unroll
    for (int r = 0; r < 8; r++) {
        const int lrow = rg * 8 + r;
        const int row = rbase + lrow;
        float4 o = *reinterpret_cast<float4*>(stg + lrow * 128 + cg * 4);
        __half2 h01 = __floats2half2_rn(o.x, o.y);
        __half2 h23 = __floats2half2_rn(o.z, o.w);
        uint2 pk;
        pk.x = *reinterpret_cast<uint32_t*>(&h01);
        pk.y = *reinterpret_cast<uint32_t*>(&h23);
        *reinterpret_cast<uint2*>(&g_bufH[(size_t)row * 128 + cg * 4]) = pk;
        float s1 = o.x * as4.x + o.y * as4.y + o.z * as4.z + o.w * as4.w;
        float s2 = o.x * ad4.x + o.y * ad4.y + o.z * ad4.z + o.w * ad4.w;
#pragma unroll
        for (int off = 1; off < 8; off <<= 1) {
            s1 += __shfl_xor_sync(0xffffffffu, s1, off);
            s2 += __shfl_xor_sync(0xffffffffu, s2, off);
        }
        if ((cg & 7) == 0) {
            g_als[row * 4 + head] = s1;
            g_ald[row * 4 + head] = s2;
        }
    }
}

// ---------------- small GEMM (layer 2): [N,128]@[128,32], fp32 h ----------------
__global__ __launch_bounds__(128) void k_gemm32(
    const float* __restrict__ W, const float* __restrict__ bprev,
    const float* __restrict__ a_src, const float* __restrict__ a_dst) {
    constexpr int M = 32;
    constexpr int RPP = 32;
    const int t = threadIdx.x;
    const int col = t % M;
    const int grp = t / M;
    __shared__ float xs[RPP][128];
    const float asv = a_src[col];
    const float adv = a_dst[col];
    const int rowblock = blockIdx.x * (4 * RPP);

    for (int pass = 0; pass < 4; ++pass) {
        const int rbase = rowblock + pass * RPP;
        __syncthreads();
        for (int j = t; j < RPP * 128; j += 128) {
            int r = rbase + (j >> 7);
            float v = (r < N_NODES) ? g_bufB[(size_t)r * 128 + (j & 127)] : 0.f;
            v += bprev[j & 127];
            v = v > 0.f ? v : expm1f(v);
            xs[j >> 7][j & 127] = v;
        }
        __syncthreads();
        float acc[8] = {0, 0, 0, 0, 0, 0, 0, 0};
        const int r0 = grp * 8;
#pragma unroll 4
        for (int k = 0; k < 128; ++k) {
            float w = W[k * M + col];
#pragma unroll
            for (int r = 0; r < 8; ++r) acc[r] += xs[r0 + r][k] * w;
        }
#pragma unroll
        for (int r = 0; r < 8; ++r) {
            int row = rbase + r0 + r;
            if (row < N_NODES) {
                g_bufA[(size_t)row * M + col] = acc[r];
                float s1 = acc[r] * asv, s2 = acc[r] * adv;
#pragma unroll
                for (int o = 16; o; o >>= 1) {
                    s1 += __shfl_xor_sync(0xffffffffu, s1, o);
                    s2 += __shfl_xor_sync(0xffffffffu, s2, o);
                }
                if (col == 0) {
                    g_als[row] = s1;
                    g_ald[row] = s2;
                }
            }
        }
    }
}

// ---------------- GAT aggregation (H=4, fp16 h): one warp per dst ----------------
__global__ __launch_bounds__(256) void k_agg4() {
    int d = (blockIdx.x * blockDim.x + threadIdx.x) >> 5;
    if (d >= N_NODES) return;
    const int lane = threadIdx.x & 31;
    const int beg = g_rs[d], end = g_rs[d + 1];
    const int head = lane >> 3;

    const float aldh = g_ald[d * 4 + head];
    float den = 0.f;
    float acc0 = 0.f, acc1 = 0.f, acc2 = 0.f, acc3 = 0.f;

    int s_next = (beg < end) ? g_srcs[beg] : 0;
    for (int j = beg; j < end; ++j) {
        const int s = s_next;
        if (j + 1 < end) s_next = g_srcs[j + 1];
        float e = g_als[s * 4 + head] + aldh;
        e = e > 0.f ? e : 0.2f * e;
        e = fminf(e, 60.f);
        float p = __expf(e);
        den += p;
        uint2 raw = *reinterpret_cast<const uint2*>(&g_bufH[(size_t)s * 128 + lane * 4]);
        __half2 h01 = *reinterpret_cast<__half2*>(&raw.x);
        __half2 h23 = *reinterpret_cast<__half2*>(&raw.y);
        float2 f01 = __half22float2(h01);
        float2 f23 = __half22float2(h23);
        acc0 += p * f01.x; acc1 += p * f01.y;
        acc2 += p * f23.x; acc3 += p * f23.y;
    }
    float inv = 1.f / fmaxf(den, 1e-16f);
    float4 o; o.x = acc0 * inv; o.y = acc1 * inv; o.z = acc2 * inv; o.w = acc3 * inv;
    *reinterpret_cast<float4*>(&g_bufB[(size_t)d * 128 + lane * 4]) = o;
}

// ---------------- GAT aggregation (H=1, fp32 h, 32 channels) ----------------
__global__ __launch_bounds__(256) void k_agg1() {
    int d = (blockIdx.x * blockDim.x + threadIdx.x) >> 5;
    if (d >= N_NODES) return;
    const int lane = threadIdx.x & 31;
    const int beg = g_rs[d], end = g_rs[d + 1];

    const float aldh = g_ald[d];
    float den = 0.f, acc = 0.f;

    int s_next = (beg < end) ? g_srcs[beg] : 0;
    for (int j = beg; j < end; ++j) {
        const int s = s_next;
        if (j + 1 < end) s_next = g_srcs[j + 1];
        float e = g_als[s] + aldh;
        e = e > 0.f ? e : 0.2f * e;
        e = fminf(e, 60.f);
        float p = __expf(e);
        den += p;
        acc += p * g_bufA[(size_t)s * 32 + lane];
    }
    g_bufB[(size_t)d * 32 + lane] = acc / fmaxf(den, 1e-16f);
}

// ---------------- global mean pool (batch sorted, fused ELU+bias) ----------------
__global__ __launch_bounds__(256) void k_pool(
    const void* __restrict__ batch, const float* __restrict__ b2) {
    const bool is64 = (g_is64 != 0);
    const int gi = blockIdx.x;
    int lo = 0, hi = N_NODES;
    while (lo < hi) { int mid = (lo + hi) >> 1;
        if (load_idx(batch, mid, is64) < gi) lo = mid + 1; else hi = mid; }
    const int start = lo;
    lo = start; hi = N_NODES;
    while (lo < hi) { int mid = (lo + hi) >> 1;
        if (load_idx(batch, mid, is64) < gi + 1) lo = mid + 1; else hi = mid; }
    const int end = lo;

    const int t = threadIdx.x;
    const int c = t & 31;
    const int sub = t >> 5;
    float acc = 0.f;
    for (int n = start + sub; n < end; n += 8) {
        float v = g_bufB[(size_t)n * 32 + c] + b2[c];
        acc += v > 0.f ? v : expm1f(v);
    }
    __shared__ float red[256];
    red[t] = acc;
    __syncthreads();
    if (sub == 0) {
        float s = 0.f;
#pragma unroll
        for (int k = 0; k < 8; k++) s += red[k * 32 + c];
        float cnt = (float)(end - start);
        g_g[blockIdx.x * 32 + c] = s / fmaxf(cnt, 1.f);
    }
}

// ---------------- final MLP: relu(g@W1+b1)@W2+b2 ----------------
__global__ __launch_bounds__(128) void k_mlp(
    const float* __restrict__ w1, const float* __restrict__ b1,
    const float* __restrict__ w2, const float* __restrict__ b2o,
    float* __restrict__ out) {
    const int gi = blockIdx.x;
    const int t = threadIdx.x;
    __shared__ float gv[32], t1[128];
    if (t < 32) gv[t] = g_g[gi * 32 + t];
    __syncthreads();
    float acc = b1[t];
#pragma unroll
    for (int c = 0; c < 32; c++) acc += gv[c] * w1[c * 128 + t];
    t1[t] = fmaxf(acc, 0.f);
    __syncthreads();
    if (t < 8) {
        float o = b2o[t];
#pragma unroll 8
        for (int j = 0; j < 128; j++) o += t1[j] * w2[j * 8 + t];
        out[gi * 8 + t] = o;
    }
}

// ---------------- launch ----------------
extern "C" void kernel_launch(void* const* d_in, const int* in_sizes, int n_in,
                              void* d_out, int out_size) {
    const float* x     = (const float*)d_in[0];
    const void*  ei    = d_in[1];
    const void*  batch = d_in[2];
    const float* W0  = (const float*)d_in[3];
    const float* as0 = (const float*)d_in[4];
    const float* ad0 = (const float*)d_in[5];
    const float* b0  = (const float*)d_in[6];
    const float* W1  = (const float*)d_in[7];
    const float* as1 = (const float*)d_in[8];
    const float* ad1 = (const float*)d_in[9];
    const float* b1  = (const float*)d_in[10];
    const float* W2  = (const float*)d_in[11];
    const float* as2 = (const float*)d_in[12];
    const float* ad2 = (const float*)d_in[13];
    const float* b2  = (const float*)d_in[14];
    const float* l1w = (const float*)d_in[15];
    const float* l1b = (const float*)d_in[16];
    const float* l2w = (const float*)d_in[17];
    const float* l2b = (const float*)d_in[18];

    const int eblk = (NE_TOT + 255) / 256;
    const int nblk = (N_PAD + 255) / 256;
    const int gemm128_blocks = N_NODES / 64;             // 625, exact
    const int gemm32_blocks  = (N_NODES + 127) / 128;
    const int agg_blocks     = (N_NODES + 7) / 8;

    // fork-join resources, created once on the (uncaptured) correctness call
    static cudaStream_t s2 = nullptr;
    static cudaEvent_t evFork = nullptr, evJoin = nullptr;
    if (s2 == nullptr) {
        cudaStreamCreateWithFlags(&s2, cudaStreamNonBlocking);
        cudaEventCreateWithFlags(&evFork, cudaEventDisableTiming);
        cudaEventCreateWithFlags(&evJoin, cudaEventDisableTiming);
    }

    // fork: CSR build on s2, GEMM0 on main stream — independent until agg0
    cudaEventRecord(evFork, 0);
    cudaStreamWaitEvent(s2, evFork, 0);

    k_zero_deg<<<nblk, 256, 0, s2>>>(1);
    k_detect<<<1, 1024, 0, s2>>>(ei);
    k_hist<<<eblk, 256, 0, s2>>>(ei);
    k_scan1<<<10, 1024, 0, s2>>>();        // local scans + zero deg
    k_scan2<<<10, 1024, 0, s2>>>();        // block offsets
    k_scatter<<<eblk, 256, 0, s2>>>(ei);
    cudaEventRecord(evJoin, s2);

    // layer 0 GEMM overlaps the CSR build
    k_gemm128_tc<false, 0><<<gemm128_blocks, 256>>>(x, W0, nullptr, as0, ad0);

    cudaStreamWaitEvent(0, evJoin, 0);     // join before first aggregation

    k_agg4<<<agg_blocks, 256>>>();
    // layer 1: elu(bufB+b0) @ W1 -> bufH, agg -> bufB
    k_gemm128_tc<true, 1><<<gemm128_blocks, 256>>>(nullptr, W1, b0, as1, ad1);
    k_agg4<<<agg_blocks, 256>>>();
    // layer 2: elu(bufB+b1) @ W2 -> bufA(32), agg -> bufB(32)
    k_gemm32<<<gemm32_blocks, 128>>>(W2, b1, as2, ad2);
    k_agg1<<<agg_blocks, 256>>>();

    // pool (fused elu+b2) + MLP
    k_pool<<<NUM_GRAPHS, 256>>>(batch, b2);
    k_mlp<<<NUM_GRAPHS, 128>>>(l1w, l1b, l2w, l2b, (float*)d_out);
}

// round 9
// speedup vs baseline: 1.4189x; 1.0018x over previous
#include <cuda_runtime.h>
#include <cuda_fp16.h>
#include <mma.h>
#include <cstdint>

using namespace nvcuda;

#define N_NODES 40000
#define N_EDGES 640000
#define NUM_GRAPHS 64
#define NE_TOT (N_EDGES + N_NODES)
#define N_PAD 40960                 // 10 * 4096, covers N_NODES

// ---------------- device scratch (referenced directly by symbol) ----------------
__device__ __half  g_bufH[N_NODES * 128];   // fp16 h for 128-wide layers (agg gather)
__device__ float g_bufA[N_NODES * 32];      // fp32 h for layer 2 (32-wide)
__device__ float g_bufB[N_NODES * 128];     // aggregation output / next input
__device__ float g_als[N_NODES * 4];
__device__ float g_ald[N_NODES * 4];
__device__ __align__(16) int g_deg[N_PAD];      // degree, then cursor (padded, zeroed)
__device__ __align__(16) int g_rs[N_PAD + 4];   // CSR row starts (by dst)
__device__ int   g_srcs[NE_TOT];            // CSR src list (incl. self loops)
__device__ float g_g[NUM_GRAPHS * 32];      // pooled graph features
__device__ int   g_is64;                    // 1 if edge_index/batch are int64
__device__ int   g_bsum[16];                // per-block scan totals (+1 sentinel)

// ---------------- index helpers ----------------
__device__ __forceinline__ int load_idx(const void* p, int i, bool is64) {
    return is64 ? (int)((const long long*)p)[i] : ((const int*)p)[i];
}

// ---------------- init: zero deg + bsum, preset is64, sample-detect dtype -----
__global__ void k_init(const void* __restrict__ ei) {
    int i = blockIdx.x * blockDim.x + threadIdx.x;
    if (i < N_PAD) g_deg[i] = 0;
    if (i < 16) g_bsum[i] = 0;
    if (i == 0) g_is64 = 1;
    if (i < 1024) {                               // sample first 1024 edges
        if (((const int*)ei)[2 * i + 1] != 0) g_is64 = 0;
    }
}

// ---------------- CSR build ----------------
__global__ void k_hist(const void* __restrict__ ei) {
    int i = blockIdx.x * blockDim.x + threadIdx.x;
    if (i >= NE_TOT) return;
    const bool is64 = (g_is64 != 0);
    int d = (i < N_EDGES) ? load_idx(ei, N_EDGES + i, is64) : (i - N_EDGES);
    if ((unsigned)d < (unsigned)N_NODES) atomicAdd(&g_deg[d], 1);
}

// single-kernel scan: 10 blocks, local scan + inter-block offset via posted
// totals (total+1 sentinel, spin-wait; all 10 blocks co-resident on 148 SMs).
// Also zeroes g_deg (cursor for scatter).
__global__ __launch_bounds__(1024) void k_scan() {
    __shared__ int wsum[32];
    __shared__ int boff;
    const int t = threadIdx.x;
    const int lane = t & 31, wid = t >> 5;
    const int b = blockIdx.x;
    const int idx = b * 1024 + t;                 // int4 index
    int4* __restrict__ deg4 = reinterpret_cast<int4*>(g_deg);
    int4* __restrict__ rs4  = reinterpret_cast<int4*>(g_rs);

    int4 v = deg4[idx];
    int s = v.x + v.y + v.z + v.w;
    int x = s;
#pragma unroll
    for (int o = 1; o < 32; o <<= 1) {
        int y = __shfl_up_sync(0xffffffffu, x, o);
        if (lane >= o) x += y;
    }
    if (lane == 31) wsum[wid] = x;
    __syncthreads();
    if (wid == 0) {
        int ws = wsum[lane];
#pragma unroll
        for (int o = 1; o < 32; o <<= 1) {
            int y = __shfl_up_sync(0xffffffffu, ws, o);
            if (lane >= o) ws += y;
        }
        wsum[lane] = ws;
    }
    __syncthreads();
    if (t == 1023) atomicExch(&g_bsum[b], wsum[31] + 1);  // post total (+1)
    if (t == 0) {
        int off = 0;
        for (int i = 0; i < b; i++) {
            int w;
            while ((w = atomicOr(&g_bsum[i], 0)) == 0) { }
            off += w - 1;
        }
        boff = off;
    }
    __syncthreads();
    int excl = boff + x - s + (wid ? wsum[wid - 1] : 0);
    int4 r;
    r.x = excl;       r.y = r.x + v.x;
    r.z = r.y + v.y;  r.w = r.z + v.z;
    rs4[idx] = r;
    deg4[idx] = make_int4(0, 0, 0, 0);
}

__global__ void k_scatter(const void* __restrict__ ei) {
    int i = blockIdx.x * blockDim.x + threadIdx.x;
    if (i >= NE_TOT) return;
    const bool is64 = (g_is64 != 0);
    int s, d;
    if (i < N_EDGES) {
        s = load_idx(ei, i, is64);
        d = load_idx(ei, N_EDGES + i, is64);
    } else {
        s = d = i - N_EDGES;
    }
    if ((unsigned)d >= (unsigned)N_NODES || (unsigned)s >= (unsigned)N_NODES) return;
    int pos = g_rs[d] + atomicAdd(&g_deg[d], 1);
    g_srcs[pos] = s;
}

// ---------------- big GEMM via HMMA: [N,128]@[128,128] ----------------
template <bool ACT, int SRC>
__global__ __launch_bounds__(256) void k_gemm128_tc(
    const float* __restrict__ xin, const float* __restrict__ W,
    const float* __restrict__ bprev,
    const float* __restrict__ a_src, const float* __restrict__ a_dst) {
    __shared__ __align__(16) char smraw[49152];
    __half* sA = reinterpret_cast<__half*>(smraw);            // [64][128]
    __half* sB = reinterpret_cast<__half*>(smraw + 16384);    // [128][128]
    float*  stg = reinterpret_cast<float*>(smraw);            // [64][128], aliases

    const int t = threadIdx.x;
    const int rbase = blockIdx.x * 64;   // 625 blocks * 64 = 40000 exactly
    const float* __restrict__ in = (SRC == 0) ? xin : g_bufB;
    const float4* __restrict__ src4 =
        reinterpret_cast<const float4*>(in + (size_t)rbase * 128);
    const float4* __restrict__ bp4 = reinterpret_cast<const float4*>(bprev);

#pragma unroll
    for (int i = 0; i < 8; i++) {
        int f = t + i * 256;
        float4 v = src4[f];
        if (ACT) {
            float4 b = bp4[f & 31];
            v.x += b.x; v.y += b.y; v.z += b.z; v.w += b.w;
            v.x = v.x > 0.f ? v.x : expm1f(v.x);
            v.y = v.y > 0.f ? v.y : expm1f(v.y);
            v.z = v.z > 0.f ? v.z : expm1f(v.z);
            v.w = v.w > 0.f ? v.w : expm1f(v.w);
        }
        __half2 h01 = __floats2half2_rn(v.x, v.y);
        __half2 h23 = __floats2half2_rn(v.z, v.w);
        uint2 pk;
        pk.x = *reinterpret_cast<uint32_t*>(&h01);
        pk.y = *reinterpret_cast<uint32_t*>(&h23);
        *reinterpret_cast<uint2*>(sA + f * 4) = pk;
    }
    const float4* __restrict__ W4 = reinterpret_cast<const float4*>(W);
#pragma unroll
    for (int i = 0; i < 16; i++) {
        int f = t + i * 256;
        float4 v = W4[f];
        __half2 h01 = __floats2half2_rn(v.x, v.y);
        __half2 h23 = __floats2half2_rn(v.z, v.w);
        uint2 pk;
        pk.x = *reinterpret_cast<uint32_t*>(&h01);
        pk.y = *reinterpret_cast<uint32_t*>(&h23);
        *reinterpret_cast<uint2*>(sB + f * 4) = pk;
    }
    __syncthreads();

    const int w = t >> 5;
    const int wr = (w >> 2) * 32;
    const int wc = (w & 3) * 32;

    wmma::fragment<wmma::accumulator, 16, 16, 16, float> acc[2][2];
#pragma unroll
    for (int i = 0; i < 2; i++)
#pragma unroll
        for (int j = 0; j < 2; j++) wmma::fill_fragment(acc[i][j], 0.f);

    wmma::fragment<wmma::matrix_a, 16, 16, 16, __half, wmma::row_major> af[2];
    wmma::fragment<wmma::matrix_b, 16, 16, 16, __half, wmma::row_major> bf[2];
#pragma unroll
    for (int k = 0; k < 8; k++) {
        wmma::load_matrix_sync(af[0], sA + (wr +  0) * 128 + k * 16, 128);
        wmma::load_matrix_sync(af[1], sA + (wr + 16) * 128 + k * 16, 128);
        wmma::load_matrix_sync(bf[0], sB + (k * 16) * 128 + wc +  0, 128);
        wmma::load_matrix_sync(bf[1], sB + (k * 16) * 128 + wc + 16, 128);
#pragma unroll
        for (int i = 0; i < 2; i++)
#pragma unroll
            for (int j = 0; j < 2; j++)
                wmma::mma_sync(acc[i][j], af[i], bf[j], acc[i][j]);
    }
    __syncthreads();
#pragma unroll
    for (int i = 0; i < 2; i++)
#pragma unroll
        for (int j = 0; j < 2; j++)
            wmma::store_matrix_sync(stg + (wr + i * 16) * 128 + wc + j * 16,
                                    acc[i][j], 128, wmma::mem_row_major);
    __syncthreads();

    const int cg = t & 31;
    const int rg = t >> 5;
    const int head = cg >> 3;
    const float4 as4 = reinterpret_cast<const float4*>(a_src)[head * 8 + (cg & 7)];
    const float4 ad4 = reinterpret_cast<const float4*>(a_dst)[head * 8 + (cg & 7)];
#pragma unroll
    for (int r = 0; r < 8; r++) {
        const int lrow = rg * 8 + r;
        const int row = rbase + lrow;
        float4 o = *reinterpret_cast<float4*>(stg + lrow * 128 + cg * 4);
        __half2 h01 = __floats2half2_rn(o.x, o.y);
        __half2 h23 = __floats2half2_rn(o.z, o.w);
        uint2 pk;
        pk.x = *reinterpret_cast<uint32_t*>(&h01);
        pk.y = *reinterpret_cast<uint32_t*>(&h23);
        *reinterpret_cast<uint2*>(&g_bufH[(size_t)row * 128 + cg * 4]) = pk;
        float s1 = o.x * as4.x + o.y * as4.y + o.z * as4.z + o.w * as4.w;
        float s2 = o.x * ad4.x + o.y * ad4.y + o.z * ad4.z + o.w * ad4.w;
#pragma unroll
        for (int off = 1; off < 8; off <<= 1) {
            s1 += __shfl_xor_sync(0xffffffffu, s1, off);
            s2 += __shfl_xor_sync(0xffffffffu, s2, off);
        }
        if ((cg & 7) == 0) {
            g_als[row * 4 + head] = s1;
            g_ald[row * 4 + head] = s2;
        }
    }
}

// ---------------- small GEMM (layer 2): [N,128]@[128,32], fp32 h ----------------
__global__ __launch_bounds__(128) void k_gemm32(
    const float* __restrict__ W, const float* __restrict__ bprev,
    const float* __restrict__ a_src, const float* __restrict__ a_dst) {
    constexpr int M = 32;
    constexpr int RPP = 32;
    const int t = threadIdx.x;
    const int col = t % M;
    const int grp = t / M;
    __shared__ float xs[RPP][128];
    const float asv = a_src[col];
    const float adv = a_dst[col];
    const int rowblock = blockIdx.x * (4 * RPP);

    for (int pass = 0; pass < 4; ++pass) {
        const int rbase = rowblock + pass * RPP;
        __syncthreads();
        for (int j = t; j < RPP * 128; j += 128) {
            int r = rbase + (j >> 7);
            float v = (r < N_NODES) ? g_bufB[(size_t)r * 128 + (j & 127)] : 0.f;
            v += bprev[j & 127];
            v = v > 0.f ? v : expm1f(v);
            xs[j >> 7][j & 127] = v;
        }
        __syncthreads();
        float acc[8] = {0, 0, 0, 0, 0, 0, 0, 0};
        const int r0 = grp * 8;
#pragma unroll 4
        for (int k = 0; k < 128; ++k) {
            float w = W[k * M + col];
#pragma unroll
            for (int r = 0; r < 8; ++r) acc[r] += xs[r0 + r][k] * w;
        }
#pragma unroll
        for (int r = 0; r < 8; ++r) {
            int row = rbase + r0 + r;
            if (row < N_NODES) {
                g_bufA[(size_t)row * M + col] = acc[r];
                float s1 = acc[r] * asv, s2 = acc[r] * adv;
#pragma unroll
                for (int o = 16; o; o >>= 1) {
                    s1 += __shfl_xor_sync(0xffffffffu, s1, o);
                    s2 += __shfl_xor_sync(0xffffffffu, s2, o);
                }
                if (col == 0) {
                    g_als[row] = s1;
                    g_ald[row] = s2;
                }
            }
        }
    }
}

// ---------------- GAT aggregation (H=4, fp16 h, unroll-2) ----------------
__global__ __launch_bounds__(256) void k_agg4() {
    int d = (blockIdx.x * blockDim.x + threadIdx.x) >> 5;
    if (d >= N_NODES) return;
    const int lane = threadIdx.x & 31;
    const int beg = g_rs[d], end = g_rs[d + 1];
    const int head = lane >> 3;

    const float aldh = g_ald[d * 4 + head];
    float den = 0.f;
    float acc0 = 0.f, acc1 = 0.f, acc2 = 0.f, acc3 = 0.f;

    int j = beg;
    for (; j + 1 < end; j += 2) {
        const int s0 = g_srcs[j];
        const int s1 = g_srcs[j + 1];
        float e0 = g_als[s0 * 4 + head] + aldh;
        float e1 = g_als[s1 * 4 + head] + aldh;
        uint2 r0 = *reinterpret_cast<const uint2*>(&g_bufH[(size_t)s0 * 128 + lane * 4]);
        uint2 r1 = *reinterpret_cast<const uint2*>(&g_bufH[(size_t)s1 * 128 + lane * 4]);
        e0 = e0 > 0.f ? e0 : 0.2f * e0;  e0 = fminf(e0, 60.f);
        e1 = e1 > 0.f ? e1 : 0.2f * e1;  e1 = fminf(e1, 60.f);
        float p0 = __expf(e0);
        float p1 = __expf(e1);
        den += p0 + p1;
        float2 a01 = __half22float2(*reinterpret_cast<__half2*>(&r0.x));
        float2 a23 = __half22float2(*reinterpret_cast<__half2*>(&r0.y));
        float2 b01 = __half22float2(*reinterpret_cast<__half2*>(&r1.x));
        float2 b23 = __half22float2(*reinterpret_cast<__half2*>(&r1.y));
        acc0 += p0 * a01.x + p1 * b01.x;
        acc1 += p0 * a01.y + p1 * b01.y;
        acc2 += p0 * a23.x + p1 * b23.x;
        acc3 += p0 * a23.y + p1 * b23.y;
    }
    if (j < end) {
        const int s = g_srcs[j];
        float e = g_als[s * 4 + head] + aldh;
        e = e > 0.f ? e : 0.2f * e;  e = fminf(e, 60.f);
        float p = __expf(e);
        den += p;
        uint2 raw = *reinterpret_cast<const uint2*>(&g_bufH[(size_t)s * 128 + lane * 4]);
        float2 f01 = __half22float2(*reinterpret_cast<__half2*>(&raw.x));
        float2 f23 = __half22float2(*reinterpret_cast<__half2*>(&raw.y));
        acc0 += p * f01.x; acc1 += p * f01.y;
        acc2 += p * f23.x; acc3 += p * f23.y;
    }
    float inv = 1.f / fmaxf(den, 1e-16f);
    float4 o; o.x = acc0 * inv; o.y = acc1 * inv; o.z = acc2 * inv; o.w = acc3 * inv;
    *reinterpret_cast<float4*>(&g_bufB[(size_t)d * 128 + lane * 4]) = o;
}

// ---------------- GAT aggregation (H=1, fp32 h, 32 ch, unroll-2) ----------------
__global__ __launch_bounds__(256) void k_agg1() {
    int d = (blockIdx.x * blockDim.x + threadIdx.x) >> 5;
    if (d >= N_NODES) return;
    const int lane = threadIdx.x & 31;
    const int beg = g_rs[d], end = g_rs[d + 1];

    const float aldh = g_ald[d];
    float den = 0.f, acc = 0.f;

    int j = beg;
    for (; j + 1 < end; j += 2) {
        const int s0 = g_srcs[j];
        const int s1 = g_srcs[j + 1];
        float e0 = g_als[s0] + aldh;
        float e1 = g_als[s1] + aldh;
        float v0 = g_bufA[(size_t)s0 * 32 + lane];
        float v1 = g_bufA[(size_t)s1 * 32 + lane];
        e0 = e0 > 0.f ? e0 : 0.2f * e0;  e0 = fminf(e0, 60.f);
        e1 = e1 > 0.f ? e1 : 0.2f * e1;  e1 = fminf(e1, 60.f);
        float p0 = __expf(e0);
        float p1 = __expf(e1);
        den += p0 + p1;
        acc += p0 * v0 + p1 * v1;
    }
    if (j < end) {
        const int s = g_srcs[j];
        float e = g_als[s] + aldh;
        e = e > 0.f ? e : 0.2f * e;  e = fminf(e, 60.f);
        float p = __expf(e);
        den += p;
        acc += p * g_bufA[(size_t)s * 32 + lane];
    }
    g_bufB[(size_t)d * 32 + lane] = acc / fmaxf(den, 1e-16f);
}

// ---------------- global mean pool (batch sorted, fused ELU+bias) ----------------
__global__ __launch_bounds__(256) void k_pool(
    const void* __restrict__ batch, const float* __restrict__ b2) {
    const bool is64 = (g_is64 != 0);
    const int gi = blockIdx.x;
    int lo = 0, hi = N_NODES;
    while (lo < hi) { int mid = (lo + hi) >> 1;
        if (load_idx(batch, mid, is64) < gi) lo = mid + 1; else hi = mid; }
    const int start = lo;
    lo = start; hi = N_NODES;
    while (lo < hi) { int mid = (lo + hi) >> 1;
        if (load_idx(batch, mid, is64) < gi + 1) lo = mid + 1; else hi = mid; }
    const int end = lo;

    const int t = threadIdx.x;
    const int c = t & 31;
    const int sub = t >> 5;
    float acc = 0.f;
    for (int n = start + sub; n < end; n += 8) {
        float v = g_bufB[(size_t)n * 32 + c] + b2[c];
        acc += v > 0.f ? v : expm1f(v);
    }
    __shared__ float red[256];
    red[t] = acc;
    __syncthreads();
    if (sub == 0) {
        float s = 0.f;
#pragma unroll
        for (int k = 0; k < 8; k++) s += red[k * 32 + c];
        float cnt = (float)(end - start);
        g_g[blockIdx.x * 32 + c] = s / fmaxf(cnt, 1.f);
    }
}

// ---------------- final MLP: relu(g@W1+b1)@W2+b2 ----------------
__global__ __launch_bounds__(128) void k_mlp(
    const float* __restrict__ w1, const float* __restrict__ b1,
    const float* __restrict__ w2, const float* __restrict__ b2o,
    float* __restrict__ out) {
    const int gi = blockIdx.x;
    const int t = threadIdx.x;
    __shared__ float gv[32], t1[128];
    if (t < 32) gv[t] = g_g[gi * 32 + t];
    __syncthreads();
    float acc = b1[t];
#pragma unroll
    for (int c = 0; c < 32; c++) acc += gv[c] * w1[c * 128 + t];
    t1[t] = fmaxf(acc, 0.f);
    __syncthreads();
    if (t < 8) {
        float o = b2o[t];
#pragma unroll 8
        for (int j = 0; j < 128; j++) o += t1[j] * w2[j * 8 + t];
        out[gi * 8 + t] = o;
    }
}

// ---------------- launch ----------------
extern "C" void kernel_launch(void* const* d_in, const int* in_sizes, int n_in,
                              void* d_out, int out_size) {
    const float* x     = (const float*)d_in[0];
    const void*  ei    = d_in[1];
    const void*  batch = d_in[2];
    const float* W0  = (const float*)d_in[3];
    const float* as0 = (const float*)d_in[4];
    const float* ad0 = (const float*)d_in[5];
    const float* b0  = (const float*)d_in[6];
    const float* W1  = (const float*)d_in[7];
    const float* as1 = (const float*)d_in[8];
    const float* ad1 = (const float*)d_in[9];
    const float* b1  = (const float*)d_in[10];
    const float* W2  = (const float*)d_in[11];
    const float* as2 = (const float*)d_in[12];
    const float* ad2 = (const float*)d_in[13];
    const float* b2  = (const float*)d_in[14];
    const float* l1w = (const float*)d_in[15];
    const float* l1b = (const float*)d_in[16];
    const float* l2w = (const float*)d_in[17];
    const float* l2b = (const float*)d_in[18];

    const int eblk = (NE_TOT + 255) / 256;
    const int nblk = (N_PAD + 255) / 256;
    const int gemm128_blocks = N_NODES / 64;             // 625, exact
    const int gemm32_blocks  = (N_NODES + 127) / 128;
    const int agg_blocks     = (N_NODES + 7) / 8;

    // fork-join resources, created once on the (uncaptured) correctness call
    static cudaStream_t s2 = nullptr;
    static cudaEvent_t evFork = nullptr, evJoin = nullptr;
    if (s2 == nullptr) {
        cudaStreamCreateWithFlags(&s2, cudaStreamNonBlocking);
        cudaEventCreateWithFlags(&evFork, cudaEventDisableTiming);
        cudaEventCreateWithFlags(&evJoin, cudaEventDisableTiming);
    }

    // launch #1: gemm0 (overlaps CSR build; also places agg4 at launch #6 for ncu)
    k_gemm128_tc<false, 0><<<gemm128_blocks, 256>>>(x, W0, nullptr, as0, ad0);

    cudaEventRecord(evFork, 0);
    cudaStreamWaitEvent(s2, evFork, 0);

    // launches #2..#5: CSR build on s2
    k_init<<<nblk, 256, 0, s2>>>(ei);
    k_hist<<<eblk, 256, 0, s2>>>(ei);
    k_scan<<<10, 1024, 0, s2>>>();         // single-kernel scan + zero cursor
    k_scatter<<<eblk, 256, 0, s2>>>(ei);
    cudaEventRecord(evJoin, s2);

    cudaStreamWaitEvent(0, evJoin, 0);     // join before first aggregation

    // launch #6: k_agg4 (profiled by ncu -s 5 -c 1)
    k_agg4<<<agg_blocks, 256>>>();
    // layer 1: elu(bufB+b0) @ W1 -> bufH, agg -> bufB
    k_gemm128_tc<true, 1><<<gemm128_blocks, 256>>>(nullptr, W1, b0, as1, ad1);
    k_agg4<<<agg_blocks, 256>>>();
    // layer 2: elu(bufB+b1) @ W2 -> bufA(32), agg -> bufB(32)
    k_gemm32<<<gemm32_blocks, 128>>>(W2, b1, as2, ad2);
    k_agg1<<<agg_blocks, 256>>>();

    // pool (fused elu+b2) + MLP
    k_pool<<<NUM_GRAPHS, 256>>>(batch, b2);
    k_mlp<<<NUM_GRAPHS, 128>>>(l1w, l1b, l2w, l2b, (float*)d_out);
}

// round 10
// speedup vs baseline: 1.8691x; 1.3173x over previous
#include <cuda_runtime.h>
#include <cuda_fp16.h>
#include <mma.h>
#include <cstdint>

using namespace nvcuda;

#define N_NODES 40000
#define N_EDGES 640000
#define NUM_GRAPHS 64
#define NE_TOT (N_EDGES + N_NODES)
#define N_PAD 40960                 // 10 * 4096, covers N_NODES

// ---------------- device scratch (referenced directly by symbol) ----------------
__device__ __half  g_bufH[N_NODES * 128];   // fp16 h for 128-wide layers (agg gather)
__device__ float g_bufA[N_NODES * 32];      // fp32 h for layer 2 (32-wide)
__device__ float g_bufB[N_NODES * 128];     // aggregation output / next input
__device__ float g_als[N_NODES * 4];
__device__ float g_ald[N_NODES * 4];
__device__ __align__(16) int g_deg[N_PAD];      // degree, then cursor (padded, zeroed)
__device__ __align__(16) int g_rs[N_PAD + 4];   // CSR row starts (by dst)
__device__ int   g_srcs[NE_TOT];            // CSR src list (incl. self loops)
__device__ float g_g[NUM_GRAPHS * 32];      // pooled graph sums (atomics)
__device__ int   g_is64;                    // 1 if edge_index/batch are int64
__device__ int   g_bsum[16];                // per-block scan totals (+1 sentinel)

// ---------------- index helpers ----------------
__device__ __forceinline__ int load_idx(const void* p, int i, bool is64) {
    return is64 ? (int)((const long long*)p)[i] : ((const int*)p)[i];
}

// ---------------- init: zero deg/bsum/g_g, preset is64, sample-detect dtype ----
__global__ void k_init(const void* __restrict__ ei) {
    int i = blockIdx.x * blockDim.x + threadIdx.x;
    if (i < N_PAD) g_deg[i] = 0;
    if (i < 16) g_bsum[i] = 0;
    if (i < NUM_GRAPHS * 32) g_g[i] = 0.f;
    if (i == 0) g_is64 = 1;
    if (i < 1024) {                               // sample first 1024 edges
        if (((const int*)ei)[2 * i + 1] != 0) g_is64 = 0;
    }
}

// ---------------- CSR build ----------------
__global__ void k_hist(const void* __restrict__ ei) {
    int i = blockIdx.x * blockDim.x + threadIdx.x;
    if (i >= NE_TOT) return;
    const bool is64 = (g_is64 != 0);
    int d = (i < N_EDGES) ? load_idx(ei, N_EDGES + i, is64) : (i - N_EDGES);
    if ((unsigned)d < (unsigned)N_NODES) atomicAdd(&g_deg[d], 1);
}

// single-kernel scan: 10 blocks, local scan + inter-block offset via posted
// totals (total+1 sentinel, spin-wait; all 10 blocks co-resident).
// Also zeroes g_deg (cursor for scatter).
__global__ __launch_bounds__(1024) void k_scan() {
    __shared__ int wsum[32];
    __shared__ int boff;
    const int t = threadIdx.x;
    const int lane = t & 31, wid = t >> 5;
    const int b = blockIdx.x;
    const int idx = b * 1024 + t;                 // int4 index
    int4* __restrict__ deg4 = reinterpret_cast<int4*>(g_deg);
    int4* __restrict__ rs4  = reinterpret_cast<int4*>(g_rs);

    int4 v = deg4[idx];
    int s = v.x + v.y + v.z + v.w;
    int x = s;
#pragma unroll
    for (int o = 1; o < 32; o <<= 1) {
        int y = __shfl_up_sync(0xffffffffu, x, o);
        if (lane >= o) x += y;
    }
    if (lane == 31) wsum[wid] = x;
    __syncthreads();
    if (wid == 0) {
        int ws = wsum[lane];
#pragma unroll
        for (int o = 1; o < 32; o <<= 1) {
            int y = __shfl_up_sync(0xffffffffu, ws, o);
            if (lane >= o) ws += y;
        }
        wsum[lane] = ws;
    }
    __syncthreads();
    if (t == 1023) atomicExch(&g_bsum[b], wsum[31] + 1);  // post total (+1)
    if (t == 0) {
        int off = 0;
        for (int i = 0; i < b; i++) {
            int w;
            while ((w = atomicOr(&g_bsum[i], 0)) == 0) { }
            off += w - 1;
        }
        boff = off;
    }
    __syncthreads();
    int excl = boff + x - s + (wid ? wsum[wid - 1] : 0);
    int4 r;
    r.x = excl;       r.y = r.x + v.x;
    r.z = r.y + v.y;  r.w = r.z + v.z;
    rs4[idx] = r;
    deg4[idx] = make_int4(0, 0, 0, 0);
}

__global__ void k_scatter(const void* __restrict__ ei) {
    int i = blockIdx.x * blockDim.x + threadIdx.x;
    if (i >= NE_TOT) return;
    const bool is64 = (g_is64 != 0);
    int s, d;
    if (i < N_EDGES) {
        s = load_idx(ei, i, is64);
        d = load_idx(ei, N_EDGES + i, is64);
    } else {
        s = d = i - N_EDGES;
    }
    if ((unsigned)d >= (unsigned)N_NODES || (unsigned)s >= (unsigned)N_NODES) return;
    int pos = g_rs[d] + atomicAdd(&g_deg[d], 1);
    g_srcs[pos] = s;
}

// ---------------- big GEMM via HMMA: [N,128]@[128,128] ----------------
template <bool ACT, int SRC>
__global__ __launch_bounds__(256) void k_gemm128_tc(
    const float* __restrict__ xin, const float* __restrict__ W,
    const float* __restrict__ bprev,
    const float* __restrict__ a_src, const float* __restrict__ a_dst) {
    __shared__ __align__(16) char smraw[49152];
    __half* sA = reinterpret_cast<__half*>(smraw);            // [64][128]
    __half* sB = reinterpret_cast<__half*>(smraw + 16384);    // [128][128]
    float*  stg = reinterpret_cast<float*>(smraw);            // [64][128], aliases

    const int t = threadIdx.x;
    const int rbase = blockIdx.x * 64;   // 625 blocks * 64 = 40000 exactly
    const float* __restrict__ in = (SRC == 0) ? xin : g_bufB;
    const float4* __restrict__ src4 =
        reinterpret_cast<const float4*>(in + (size_t)rbase * 128);
    const float4* __restrict__ bp4 = reinterpret_cast<const float4*>(bprev);

#pragma unroll
    for (int i = 0; i < 8; i++) {
        int f = t + i * 256;
        float4 v = src4[f];
        if (ACT) {
            float4 b = bp4[f & 31];
            v.x += b.x; v.y += b.y; v.z += b.z; v.w += b.w;
            v.x = v.x > 0.f ? v.x : expm1f(v.x);
            v.y = v.y > 0.f ? v.y : expm1f(v.y);
            v.z = v.z > 0.f ? v.z : expm1f(v.z);
            v.w = v.w > 0.f ? v.w : expm1f(v.w);
        }
        __half2 h01 = __floats2half2_rn(v.x, v.y);
        __half2 h23 = __floats2half2_rn(v.z, v.w);
        uint2 pk;
        pk.x = *reinterpret_cast<uint32_t*>(&h01);
        pk.y = *reinterpret_cast<uint32_t*>(&h23);
        *reinterpret_cast<uint2*>(sA + f * 4) = pk;
    }
    const float4* __restrict__ W4 = reinterpret_cast<const float4*>(W);
#pragma unroll
    for (int i = 0; i < 16; i++) {
        int f = t + i * 256;
        float4 v = W4[f];
        __half2 h01 = __floats2half2_rn(v.x, v.y);
        __half2 h23 = __floats2half2_rn(v.z, v.w);
        uint2 pk;
        pk.x = *reinterpret_cast<uint32_t*>(&h01);
        pk.y = *reinterpret_cast<uint32_t*>(&h23);
        *reinterpret_cast<uint2*>(sB + f * 4) = pk;
    }
    __syncthreads();

    const int w = t >> 5;
    const int wr = (w >> 2) * 32;
    const int wc = (w & 3) * 32;

    wmma::fragment<wmma::accumulator, 16, 16, 16, float> acc[2][2];
#pragma unroll
    for (int i = 0; i < 2; i++)
#pragma unroll
        for (int j = 0; j < 2; j++) wmma::fill_fragment(acc[i][j], 0.f);

    wmma::fragment<wmma::matrix_a, 16, 16, 16, __half, wmma::row_major> af[2];
    wmma::fragment<wmma::matrix_b, 16, 16, 16, __half, wmma::row_major> bf[2];
#pragma unroll
    for (int k = 0; k < 8; k++) {
        wmma::load_matrix_sync(af[0], sA + (wr +  0) * 128 + k * 16, 128);
        wmma::load_matrix_sync(af[1], sA + (wr + 16) * 128 + k * 16, 128);
        wmma::load_matrix_sync(bf[0], sB + (k * 16) * 128 + wc +  0, 128);
        wmma::load_matrix_sync(bf[1], sB + (k * 16) * 128 + wc + 16, 128);
#pragma unroll
        for (int i = 0; i < 2; i++)
#pragma unroll
            for (int j = 0; j < 2; j++)
                wmma::mma_sync(acc[i][j], af[i], bf[j], acc[i][j]);
    }
    __syncthreads();
#pragma unroll
    for (int i = 0; i < 2; i++)
#pragma unroll
        for (int j = 0; j < 2; j++)
            wmma::store_matrix_sync(stg + (wr + i * 16) * 128 + wc + j * 16,
                                    acc[i][j], 128, wmma::mem_row_major);
    __syncthreads();

    const int cg = t & 31;
    const int rg = t >> 5;
    const int head = cg >> 3;
    const float4 as4 = reinterpret_cast<const float4*>(a_src)[head * 8 + (cg & 7)];
    const float4 ad4 = reinterpret_cast<const float4*>(a_dst)[head * 8 + (cg & 7)];
#pragma unroll
    for (int r = 0; r < 8; r++) {
        const int lrow = rg * 8 + r;
        const int row = rbase + lrow;
        float4 o = *reinterpret_cast<float4*>(stg + lrow * 128 + cg * 4);
        __half2 h01 = __floats2half2_rn(o.x, o.y);
        __half2 h23 = __floats2half2_rn(o.z, o.w);
        uint2 pk;
        pk.x = *reinterpret_cast<uint32_t*>(&h01);
        pk.y = *reinterpret_cast<uint32_t*>(&h23);
        *reinterpret_cast<uint2*>(&g_bufH[(size_t)row * 128 + cg * 4]) = pk;
        float s1 = o.x * as4.x + o.y * as4.y + o.z * as4.z + o.w * as4.w;
        float s2 = o.x * ad4.x + o.y * ad4.y + o.z * ad4.z + o.w * ad4.w;
#pragma unroll
        for (int off = 1; off < 8; off <<= 1) {
            s1 += __shfl_xor_sync(0xffffffffu, s1, off);
            s2 += __shfl_xor_sync(0xffffffffu, s2, off);
        }
        if ((cg & 7) == 0) {
            g_als[row * 4 + head] = s1;
            g_ald[row * 4 + head] = s2;
        }
    }
}

// ---------------- layer-2 GEMM via HMMA: [N,128]@[128,32], fp32 h out ----------
__global__ __launch_bounds__(256) void k_gemm32_tc(
    const float* __restrict__ W, const float* __restrict__ bprev,
    const float* __restrict__ a_src, const float* __restrict__ a_dst) {
    __shared__ __align__(16) char smraw[32768];
    __half* sA = reinterpret_cast<__half*>(smraw);            // [64][128] 16KB
    __half* sB = reinterpret_cast<__half*>(smraw + 16384);    // [128][32]  8KB
    float*  stg = reinterpret_cast<float*>(smraw + 24576);    // [64][32]   8KB

    const int t = threadIdx.x;
    const int rbase = blockIdx.x * 64;   // 625 blocks
    const float4* __restrict__ src4 =
        reinterpret_cast<const float4*>(g_bufB + (size_t)rbase * 128);
    const float4* __restrict__ bp4 = reinterpret_cast<const float4*>(bprev);

    // x tile (+ELU+b1) -> fp16 smem
#pragma unroll
    for (int i = 0; i < 8; i++) {
        int f = t + i * 256;
        float4 v = src4[f];
        float4 b = bp4[f & 31];
        v.x += b.x; v.y += b.y; v.z += b.z; v.w += b.w;
        v.x = v.x > 0.f ? v.x : expm1f(v.x);
        v.y = v.y > 0.f ? v.y : expm1f(v.y);
        v.z = v.z > 0.f ? v.z : expm1f(v.z);
        v.w = v.w > 0.f ? v.w : expm1f(v.w);
        __half2 h01 = __floats2half2_rn(v.x, v.y);
        __half2 h23 = __floats2half2_rn(v.z, v.w);
        uint2 pk;
        pk.x = *reinterpret_cast<uint32_t*>(&h01);
        pk.y = *reinterpret_cast<uint32_t*>(&h23);
        *reinterpret_cast<uint2*>(sA + f * 4) = pk;
    }
    // W2 (128x32) -> fp16 smem
    const float4* __restrict__ W4 = reinterpret_cast<const float4*>(W);
#pragma unroll
    for (int i = 0; i < 4; i++) {
        int f = t + i * 256;               // 1024 float4s
        float4 v = W4[f];
        __half2 h01 = __floats2half2_rn(v.x, v.y);
        __half2 h23 = __floats2half2_rn(v.z, v.w);
        uint2 pk;
        pk.x = *reinterpret_cast<uint32_t*>(&h01);
        pk.y = *reinterpret_cast<uint32_t*>(&h23);
        *reinterpret_cast<uint2*>(sB + f * 4) = pk;
    }
    __syncthreads();

    // 8 warps: 4 row tiles x 2 col tiles of 16x16
    const int w = t >> 5;
    const int wr = (w >> 1) * 16;
    const int wc = (w & 1) * 16;
    wmma::fragment<wmma::accumulator, 16, 16, 16, float> acc;
    wmma::fill_fragment(acc, 0.f);
    wmma::fragment<wmma::matrix_a, 16, 16, 16, __half, wmma::row_major> af;
    wmma::fragment<wmma::matrix_b, 16, 16, 16, __half, wmma::row_major> bf;
#pragma unroll
    for (int k = 0; k < 8; k++) {
        wmma::load_matrix_sync(af, sA + wr * 128 + k * 16, 128);
        wmma::load_matrix_sync(bf, sB + (k * 16) * 32 + wc, 32);
        wmma::mma_sync(acc, af, bf, acc);
    }
    wmma::store_matrix_sync(stg + wr * 32 + wc, acc, 32, wmma::mem_row_major);
    __syncthreads();

    // epilogue: fp32 h store + fused als/ald (H=1, reduce over 32 cols)
    const int col = t & 31;
    const int rg = t >> 5;
    const float asv = a_src[col];
    const float adv = a_dst[col];
#pragma unroll
    for (int r = 0; r < 8; r++) {
        const int lrow = rg * 8 + r;
        const int row = rbase + lrow;
        float v = stg[lrow * 32 + col];
        g_bufA[(size_t)row * 32 + col] = v;
        float s1 = v * asv, s2 = v * adv;
#pragma unroll
        for (int o = 16; o; o >>= 1) {
            s1 += __shfl_xor_sync(0xffffffffu, s1, o);
            s2 += __shfl_xor_sync(0xffffffffu, s2, o);
        }
        if (col == 0) {
            g_als[row] = s1;
            g_ald[row] = s2;
        }
    }
}

// ---------------- GAT aggregation (H=4, fp16 h, unroll-2) ----------------
__global__ __launch_bounds__(256) void k_agg4() {
    int d = (blockIdx.x * blockDim.x + threadIdx.x) >> 5;
    if (d >= N_NODES) return;
    const int lane = threadIdx.x & 31;
    const int beg = g_rs[d], end = g_rs[d + 1];
    const int head = lane >> 3;

    const float aldh = g_ald[d * 4 + head];
    float den = 0.f;
    float acc0 = 0.f, acc1 = 0.f, acc2 = 0.f, acc3 = 0.f;

    int j = beg;
    for (; j + 1 < end; j += 2) {
        const int s0 = g_srcs[j];
        const int s1 = g_srcs[j + 1];
        float e0 = g_als[s0 * 4 + head] + aldh;
        float e1 = g_als[s1 * 4 + head] + aldh;
        uint2 r0 = *reinterpret_cast<const uint2*>(&g_bufH[(size_t)s0 * 128 + lane * 4]);
        uint2 r1 = *reinterpret_cast<const uint2*>(&g_bufH[(size_t)s1 * 128 + lane * 4]);
        e0 = e0 > 0.f ? e0 : 0.2f * e0;  e0 = fminf(e0, 60.f);
        e1 = e1 > 0.f ? e1 : 0.2f * e1;  e1 = fminf(e1, 60.f);
        float p0 = __expf(e0);
        float p1 = __expf(e1);
        den += p0 + p1;
        float2 a01 = __half22float2(*reinterpret_cast<__half2*>(&r0.x));
        float2 a23 = __half22float2(*reinterpret_cast<__half2*>(&r0.y));
        float2 b01 = __half22float2(*reinterpret_cast<__half2*>(&r1.x));
        float2 b23 = __half22float2(*reinterpret_cast<__half2*>(&r1.y));
        acc0 += p0 * a01.x + p1 * b01.x;
        acc1 += p0 * a01.y + p1 * b01.y;
        acc2 += p0 * a23.x + p1 * b23.x;
        acc3 += p0 * a23.y + p1 * b23.y;
    }
    if (j < end) {
        const int s = g_srcs[j];
        float e = g_als[s * 4 + head] + aldh;
        e = e > 0.f ? e : 0.2f * e;  e = fminf(e, 60.f);
        float p = __expf(e);
        den += p;
        uint2 raw = *reinterpret_cast<const uint2*>(&g_bufH[(size_t)s * 128 + lane * 4]);
        float2 f01 = __half22float2(*reinterpret_cast<__half2*>(&raw.x));
        float2 f23 = __half22float2(*reinterpret_cast<__half2*>(&raw.y));
        acc0 += p * f01.x; acc1 += p * f01.y;
        acc2 += p * f23.x; acc3 += p * f23.y;
    }
    float inv = 1.f / fmaxf(den, 1e-16f);
    float4 o; o.x = acc0 * inv; o.y = acc1 * inv; o.z = acc2 * inv; o.w = acc3 * inv;
    *reinterpret_cast<float4*>(&g_bufB[(size_t)d * 128 + lane * 4]) = o;
}

// ---------------- GAT aggregation (H=1) + fused ELU+bias + mean-pool sums -----
__global__ __launch_bounds__(256) void k_agg1(
    const void* __restrict__ batch, const float* __restrict__ b2) {
    int d = (blockIdx.x * blockDim.x + threadIdx.x) >> 5;
    if (d >= N_NODES) return;
    const int lane = threadIdx.x & 31;
    const int beg = g_rs[d], end = g_rs[d + 1];

    const float aldh = g_ald[d];
    float den = 0.f, acc = 0.f;

    int j = beg;
    for (; j + 1 < end; j += 2) {
        const int s0 = g_srcs[j];
        const int s1 = g_srcs[j + 1];
        float e0 = g_als[s0] + aldh;
        float e1 = g_als[s1] + aldh;
        float v0 = g_bufA[(size_t)s0 * 32 + lane];
        float v1 = g_bufA[(size_t)s1 * 32 + lane];
        e0 = e0 > 0.f ? e0 : 0.2f * e0;  e0 = fminf(e0, 60.f);
        e1 = e1 > 0.f ? e1 : 0.2f * e1;  e1 = fminf(e1, 60.f);
        float p0 = __expf(e0);
        float p1 = __expf(e1);
        den += p0 + p1;
        acc += p0 * v0 + p1 * v1;
    }
    if (j < end) {
        const int s = g_srcs[j];
        float e = g_als[s] + aldh;
        e = e > 0.f ? e : 0.2f * e;  e = fminf(e, 60.f);
        float p = __expf(e);
        den += p;
        acc += p * g_bufA[(size_t)s * 32 + lane];
    }
    float v = acc / fmaxf(den, 1e-16f);
    v += b2[lane];
    v = v > 0.f ? v : expm1f(v);
    const int bd = load_idx(batch, d, g_is64 != 0);
    atomicAdd(&g_g[bd * 32 + lane], v);
}

// ---------------- final MLP: relu((g/cnt)@W1+b1)@W2+b2 ----------------
__global__ __launch_bounds__(128) void k_mlp(
    const void* __restrict__ batch,
    const float* __restrict__ w1, const float* __restrict__ b1,
    const float* __restrict__ w2, const float* __restrict__ b2o,
    float* __restrict__ out) {
    const int gi = blockIdx.x;
    const int t = threadIdx.x;
    __shared__ float gv[32], t1[128];
    __shared__ int cnt_s;
    if (t == 0) {
        const bool is64 = (g_is64 != 0);
        int lo = 0, hi = N_NODES;
        while (lo < hi) { int mid = (lo + hi) >> 1;
            if (load_idx(batch, mid, is64) < gi) lo = mid + 1; else hi = mid; }
        int start = lo;
        lo = start; hi = N_NODES;
        while (lo < hi) { int mid = (lo + hi) >> 1;
            if (load_idx(batch, mid, is64) < gi + 1) lo = mid + 1; else hi = mid; }
        cnt_s = lo - start;
    }
    __syncthreads();
    if (t < 32) gv[t] = g_g[gi * 32 + t] / fmaxf((float)cnt_s, 1.f);
    __syncthreads();
    float acc = b1[t];
#pragma unroll
    for (int c = 0; c < 32; c++) acc += gv[c] * w1[c * 128 + t];
    t1[t] = fmaxf(acc, 0.f);
    __syncthreads();
    if (t < 8) {
        float o = b2o[t];
#pragma unroll 8
        for (int j = 0; j < 128; j++) o += t1[j] * w2[j * 8 + t];
        out[gi * 8 + t] = o;
    }
}

// ---------------- launch ----------------
extern "C" void kernel_launch(void* const* d_in, const int* in_sizes, int n_in,
                              void* d_out, int out_size) {
    const float* x     = (const float*)d_in[0];
    const void*  ei    = d_in[1];
    const void*  batch = d_in[2];
    const float* W0  = (const float*)d_in[3];
    const float* as0 = (const float*)d_in[4];
    const float* ad0 = (const float*)d_in[5];
    const float* b0  = (const float*)d_in[6];
    const float* W1  = (const float*)d_in[7];
    const float* as1 = (const float*)d_in[8];
    const float* ad1 = (const float*)d_in[9];
    const float* b1  = (const float*)d_in[10];
    const float* W2  = (const float*)d_in[11];
    const float* as2 = (const float*)d_in[12];
    const float* ad2 = (const float*)d_in[13];
    const float* b2  = (const float*)d_in[14];
    const float* l1w = (const float*)d_in[15];
    const float* l1b = (const float*)d_in[16];
    const float* l2w = (const float*)d_in[17];
    const float* l2b = (const float*)d_in[18];

    const int eblk = (NE_TOT + 255) / 256;
    const int nblk = (N_PAD + 255) / 256;
    const int gemm_blocks = N_NODES / 64;                // 625, exact
    const int agg_blocks  = (N_NODES + 7) / 8;

    // fork-join resources, created once on the (uncaptured) correctness call
    static cudaStream_t s2 = nullptr;
    static cudaEvent_t evFork = nullptr, evJoin = nullptr;
    if (s2 == nullptr) {
        cudaStreamCreateWithFlags(&s2, cudaStreamNonBlocking);
        cudaEventCreateWithFlags(&evFork, cudaEventDisableTiming);
        cudaEventCreateWithFlags(&evJoin, cudaEventDisableTiming);
    }

    // gemm0 overlaps the CSR build
    k_gemm128_tc<false, 0><<<gemm_blocks, 256>>>(x, W0, nullptr, as0, ad0);

    cudaEventRecord(evFork, 0);
    cudaStreamWaitEvent(s2, evFork, 0);

    k_init<<<nblk, 256, 0, s2>>>(ei);
    k_hist<<<eblk, 256, 0, s2>>>(ei);
    k_scan<<<10, 1024, 0, s2>>>();         // single-kernel scan + zero cursor
    k_scatter<<<eblk, 256, 0, s2>>>(ei);
    cudaEventRecord(evJoin, s2);

    cudaStreamWaitEvent(0, evJoin, 0);     // join before first aggregation

    k_agg4<<<agg_blocks, 256>>>();
    // layer 1: elu(bufB+b0) @ W1 -> bufH, agg -> bufB
    k_gemm128_tc<true, 1><<<gemm_blocks, 256>>>(nullptr, W1, b0, as1, ad1);
    k_agg4<<<agg_blocks, 256>>>();
    // layer 2: elu(bufB+b1) @ W2 -> bufA(32), agg+elu+pool-sums
    k_gemm32_tc<<<gemm_blocks, 256>>>(W2, b1, as2, ad2);
    k_agg1<<<agg_blocks, 256>>>(batch, b2);

    // MLP (divides pooled sums by counts)
    k_mlp<<<NUM_GRAPHS, 128>>>(batch, l1w, l1b, l2w, l2b, (float*)d_out);
}